// round 14
// baseline (speedup 1.0000x reference)
#include <cuda_runtime.h>
#include <cuda_fp16.h>
#include <math.h>
#include <cfloat>
#include <stdint.h>

// ---------------- problem dims (fixed) ----------------
#define NTOT  65536      // nodes per side (B*N)
#define NEDGE 524288     // edges per side
#define NB    128        // graphs
#define NPG   512        // nodes per graph
#define D_F1  128
#define D_F2  96
#define D_F3  64
#define D_BINS 16

// ---------------- device scratch (per-side slabs for batched launches) -----
__device__ float g_bufA[2][NTOT * D_F1];
__device__ float g_bufB[2][NTOT * D_F1];
__device__ float g_feat[2][NTOT * D_F3];
__device__ float g_dinv[2][NTOT];
__device__ int   g_degi[2][NTOT];
__device__ int   g_row[2][NTOT + 1];
__device__ int   g_cursor[2][NTOT];
__device__ int   g_bsum[2][256];
__device__ int2  g_epack[2][NEDGE];                  // {src, norm bits}
__device__ __half g_simh[(size_t)NB * NPG * NPG];   // fp16 similarity scores
__device__ float g_smin[NB];
__device__ float g_smax[NB];
__device__ float g_pool[2][NB * D_F3];

__device__ __forceinline__ float sigmoidf_(float x) { return 1.0f / (1.0f + expf(-x)); }

__device__ __forceinline__ void atomicMinFloat(float* addr, float val) {
    int old = __float_as_int(*addr);
    while (__int_as_float(old) > val) {
        int assumed = old;
        old = atomicCAS((int*)addr, assumed, __float_as_int(val));
        if (old == assumed) break;
    }
}
__device__ __forceinline__ void atomicMaxFloat(float* addr, float val) {
    int old = __float_as_int(*addr);
    while (__int_as_float(old) < val) {
        int assumed = old;
        old = atomicCAS((int*)addr, assumed, __float_as_int(val));
        if (old == assumed) break;
    }
}

// ---------------- bf16x3 helpers (fp32 emulation via bf16 split) -----------
__device__ __forceinline__ void split2(float x0, float x1, uint32_t& h, uint32_t& l) {
    asm("cvt.rn.bf16x2.f32 %0, %1, %2;" : "=r"(h) : "f"(x1), "f"(x0));
    float r0 = x0 - __uint_as_float(h << 16);
    float r1 = x1 - __uint_as_float(h & 0xffff0000u);
    asm("cvt.rn.bf16x2.f32 %0, %1, %2;" : "=r"(l) : "f"(r1), "f"(r0));
}
__device__ __forceinline__ void mma_bf16(float* d, const uint32_t* a, const uint32_t* b) {
    asm volatile(
        "mma.sync.aligned.m16n8k16.row.col.f32.bf16.bf16.f32 "
        "{%0,%1,%2,%3}, {%4,%5,%6,%7}, {%8,%9}, {%0,%1,%2,%3};\n"
        : "+f"(d[0]), "+f"(d[1]), "+f"(d[2]), "+f"(d[3])
        : "r"(a[0]), "r"(a[1]), "r"(a[2]), "r"(a[3]), "r"(b[0]), "r"(b[1]));
}

// block-wide exclusive scan of 256 ints (one value per thread)
__device__ __forceinline__ int block_exscan_256(int v, int* sm8) {
    int lane = threadIdx.x & 31, w = threadIdx.x >> 5;
    int x = v;
#pragma unroll
    for (int o = 1; o < 32; o <<= 1) {
        int y = __shfl_up_sync(0xffffffffu, x, o);
        if (lane >= o) x += y;
    }
    if (lane == 31) sm8[w] = x;
    __syncthreads();
    if (threadIdx.x < 8) {
        int s = sm8[threadIdx.x];
#pragma unroll
        for (int o = 1; o < 8; o <<= 1) {
            int y = __shfl_up_sync(0xffu, s, o);
            if ((int)threadIdx.x >= o) s += y;
        }
        sm8[threadIdx.x] = s;
    }
    __syncthreads();
    int woff = w ? sm8[w - 1] : 0;
    return woff + x - v;
}

// ---------------- init ----------------
__global__ void init_k() {
    int i = blockIdx.x * blockDim.x + threadIdx.x;
    if (i < NTOT) { g_degi[0][i] = 0; g_degi[1][i] = 0; }
    if (i < NB) { g_smin[i] = FLT_MAX; g_smax[i] = -FLT_MAX; }
}

// ---------------- degree (both sides via grid.y) ----------------
__global__ void deg_k(const int* __restrict__ dst0, const int* __restrict__ dst1) {
    int side = blockIdx.y;
    const int* dst = side ? dst1 : dst0;
    int e = blockIdx.x * blockDim.x + threadIdx.x;
    if (e < NEDGE) atomicAdd(&g_degi[side][dst[e]], 1);
}

// ---------------- 2-phase parallel scan (A computes dinv + block sums) -----
__global__ void scanA_k() {
    int side = blockIdx.y;
    int i = blockIdx.x * 256 + threadIdx.x;
    int v = g_degi[side][i];
    g_dinv[side][i] = rsqrtf((float)v + 1.0f);
#pragma unroll
    for (int o = 16; o; o >>= 1) v += __shfl_xor_sync(0xffffffffu, v, o);
    __shared__ int sm[8];
    if ((threadIdx.x & 31) == 0) sm[threadIdx.x >> 5] = v;
    __syncthreads();
    if (threadIdx.x == 0) {
        int s = 0;
#pragma unroll
        for (int j = 0; j < 8; j++) s += sm[j];
        g_bsum[side][blockIdx.x] = s;
    }
}
__global__ void scanC_k() {
    int side = blockIdx.y;
    int bid = blockIdx.x;
    int t = threadIdx.x;
    int lane = t & 31, w = t >> 5;
    int pv = (t < bid) ? g_bsum[side][t] : 0;
#pragma unroll
    for (int o = 16; o; o >>= 1) pv += __shfl_xor_sync(0xffffffffu, pv, o);
    __shared__ int rsm[8];
    if (lane == 0) rsm[w] = pv;
    __syncthreads();
    __shared__ int prefix_s;
    if (t == 0) {
        int s = 0;
#pragma unroll
        for (int j = 0; j < 8; j++) s += rsm[j];
        prefix_s = s;
    }
    __syncthreads();
    int prefix = prefix_s;
    int i = bid * 256 + t;
    int d = g_degi[side][i];
    __shared__ int sm[8];
    int ex = block_exscan_256(d, sm);
    int off = prefix + ex;
    g_row[side][i] = off;
    g_cursor[side][i] = off;
    if (i == NTOT - 1) g_row[side][NTOT] = NEDGE;
}

// ---------------- scatter edges into CSR order (packed src+norm) -----------
__global__ void scatter_k(const int* __restrict__ ei0, const int* __restrict__ ei1) {
    int side = blockIdx.y;
    const int* ei = side ? ei1 : ei0;
    const int* src = ei;
    const int* dst = ei + NEDGE;
    int e = blockIdx.x * blockDim.x + threadIdx.x;
    if (e >= NEDGE) return;
    int s = src[e], d = dst[e];
    int pos = atomicAdd(&g_cursor[side][d], 1);
    float nm = g_dinv[side][s] * g_dinv[side][d];
    g_epack[side][pos] = make_int2(s, __float_as_int(nm));
}

// ---------------- graph-per-block aggregation, 4-chunk grouping ------------
// Each thread handles 4 float4 chunks of one node: edge list read ONCE per
// group instead of once per chunk (epack LDG traffic /4).
template <int OUT, bool BIAS, bool RELU>
__global__ void agg_k(const float* __restrict__ xw0, const float* __restrict__ xw1,
                      const float* __restrict__ bias,
                      float* __restrict__ out0, float* __restrict__ out1) {
    constexpr int C4 = OUT / 4;
    constexpr int NG = C4 / 4;          // groups of 4 float4 chunks
    int side = blockIdx.y;
    const float* xw = side ? xw1 : xw0;
    float* out = side ? out1 : out0;
    int base = blockIdx.x * NPG;
    const float4* xw4 = (const float4*)xw;
    float4* out4 = (float4*)out;
    for (int wi = threadIdx.x; wi < NPG * NG; wi += blockDim.x) {
        int node = base + wi / NG;
        int bc = (wi % NG) * 4;         // first chunk of the group
        float dv = g_dinv[side][node];
        float dv2 = dv * dv;
        float4 acc[4];
#pragma unroll
        for (int j = 0; j < 4; j++) {
            float4 v = xw4[(size_t)node * C4 + bc + j];
            acc[j] = make_float4(v.x * dv2, v.y * dv2, v.z * dv2, v.w * dv2);
        }
        int beg = g_row[side][node], end = g_row[side][node + 1];
        for (int e = beg; e < end; e++) {
            int2 ep = g_epack[side][e];
            float nm = __int_as_float(ep.y);
            size_t sb = (size_t)ep.x * C4 + bc;
#pragma unroll
            for (int j = 0; j < 4; j++) {
                float4 u = xw4[sb + j];
                acc[j].x += u.x * nm; acc[j].y += u.y * nm;
                acc[j].z += u.z * nm; acc[j].w += u.w * nm;
            }
        }
#pragma unroll
        for (int j = 0; j < 4; j++) {
            if (BIAS) {
                acc[j].x += bias[(bc + j) * 4 + 0];
                acc[j].y += bias[(bc + j) * 4 + 1];
                acc[j].z += bias[(bc + j) * 4 + 2];
                acc[j].w += bias[(bc + j) * 4 + 3];
            }
            if (RELU) {
                acc[j].x = fmaxf(acc[j].x, 0.f); acc[j].y = fmaxf(acc[j].y, 0.f);
                acc[j].z = fmaxf(acc[j].z, 0.f); acc[j].w = fmaxf(acc[j].w, 0.f);
            }
            out4[(size_t)node * C4 + bc + j] = acc[j];
        }
    }
}

// ---------------- agg3 + attention pool fused (one block per graph) --------
__global__ void agg_pool_k(const float* __restrict__ xw0, const float* __restrict__ xw1,
                           const float* __restrict__ bias,
                           float* __restrict__ out0, float* __restrict__ out1,
                           const float* __restrict__ Watt) {
    constexpr int C4 = 16, NG = 4;
    extern __shared__ float sfeat[];       // NPG*64 floats = 128 KB
    int side = blockIdx.y;
    int b = blockIdx.x;
    const float* xw = side ? xw1 : xw0;
    float* out = side ? out1 : out0;
    int base = b * NPG;
    const float4* xw4 = (const float4*)xw;
    float4* out4 = (float4*)out;
    float4* sf4 = (float4*)sfeat;
    int t = threadIdx.x;                    // 1024

    // ---- aggregation with 4-chunk grouping ----
    for (int wi = t; wi < NPG * NG; wi += 1024) {
        int lnode = wi / NG;
        int node = base + lnode;
        int bc = (wi % NG) * 4;
        float dv = g_dinv[side][node];
        float dv2 = dv * dv;
        float4 acc[4];
#pragma unroll
        for (int j = 0; j < 4; j++) {
            float4 v = xw4[(size_t)node * C4 + bc + j];
            acc[j] = make_float4(v.x * dv2, v.y * dv2, v.z * dv2, v.w * dv2);
        }
        int beg = g_row[side][node], end = g_row[side][node + 1];
        for (int e = beg; e < end; e++) {
            int2 ep = g_epack[side][e];
            float nm = __int_as_float(ep.y);
            size_t sb = (size_t)ep.x * C4 + bc;
#pragma unroll
            for (int j = 0; j < 4; j++) {
                float4 u = xw4[sb + j];
                acc[j].x += u.x * nm; acc[j].y += u.y * nm;
                acc[j].z += u.z * nm; acc[j].w += u.w * nm;
            }
        }
#pragma unroll
        for (int j = 0; j < 4; j++) {
            acc[j].x += bias[(bc + j) * 4 + 0];
            acc[j].y += bias[(bc + j) * 4 + 1];
            acc[j].z += bias[(bc + j) * 4 + 2];
            acc[j].w += bias[(bc + j) * 4 + 3];
            out4[(size_t)node * C4 + bc + j] = acc[j];
            sf4[lnode * C4 + bc + j] = acc[j];
        }
    }
    __syncthreads();

    // ---- attention pooling on the smem slab ----
    __shared__ float p16[16][64];
    __shared__ float meanc[64];
    __shared__ float ctx[64];
    __shared__ float wsum[32][64];
    int d = t & 63, g = t >> 6;
    float loc = 0.0f;
    for (int r = g; r < NPG; r += 16) loc += sfeat[r * 64 + d];
    p16[g][d] = loc;
    __syncthreads();
    if (t < 64) {
        float s = 0.0f;
#pragma unroll
        for (int j = 0; j < 16; j++) s += p16[j][t];
        meanc[t] = s * (1.0f / NPG);
    }
    __syncthreads();
    if (t < 64) {
        float c = 0.0f;
        for (int i = 0; i < 64; i++) c += meanc[i] * Watt[i * 64 + t];
        ctx[t] = tanhf(c);
    }
    __syncthreads();
    int w = t >> 5, l = t & 31;
    float a0 = 0.0f, a1 = 0.0f;
    float c0 = ctx[l], c1 = ctx[l + 32];
    for (int r = w * 16; r < w * 16 + 16; r++) {
        float v0 = sfeat[r * 64 + l], v1 = sfeat[r * 64 + 32 + l];
        float dp = v0 * c0 + v1 * c1;
#pragma unroll
        for (int o = 16; o; o >>= 1) dp += __shfl_xor_sync(0xffffffffu, dp, o);
        float coef = sigmoidf_(dp);
        a0 += v0 * coef;
        a1 += v1 * coef;
    }
    wsum[w][l] = a0;
    wsum[w][l + 32] = a1;
    __syncthreads();
    if (t < 64) {
        float s = 0.0f;
#pragma unroll
        for (int w2 = 0; w2 < 32; w2++) s += wsum[w2][t];
        g_pool[side][b * 64 + t] = s;
    }
}

// ---------------- bf16x3 tensor-core GEMM (both sides via grid.y) ----------
template <int KIN, int NOUT, bool BIAS, bool RELU>
__global__ void gemm_mma_k(const float* __restrict__ x0, const float* __restrict__ x1,
                           const float* __restrict__ W, const float* __restrict__ bias,
                           float* __restrict__ out0, float* __restrict__ out1) {
    constexpr int KC = 32;
    constexpr int KP = KC / 2;
    constexpr int NT = NOUT / 8;
    constexpr int XS = 20;
    constexpr int WS = 20;
    __shared__ uint32_t Xh[128 * XS];
    __shared__ uint32_t Xl[128 * XS];
    __shared__ uint32_t Wh[NOUT * WS];
    __shared__ uint32_t Wl[NOUT * WS];
    int side = blockIdx.y;
    const float* x = side ? x1 : x0;
    float* out = side ? out1 : out0;
    int tid = threadIdx.x;
    int warp = tid >> 5, lane = tid & 31;
    size_t m0 = (size_t)blockIdx.x * 128;
    float acc[NT][4];
#pragma unroll
    for (int i = 0; i < NT; i++)
#pragma unroll
        for (int j = 0; j < 4; j++) acc[i][j] = 0.0f;

    for (int k0 = 0; k0 < KIN; k0 += KC) {
        for (int i = tid; i < 128 * 8; i += 256) {
            int r = i >> 3, q = i & 7;
            float4 v = *(const float4*)&x[(m0 + r) * KIN + k0 + q * 4];
            uint32_t h0, l0, h1, l1;
            split2(v.x, v.y, h0, l0);
            split2(v.z, v.w, h1, l1);
            Xh[r * XS + q * 2] = h0;     Xh[r * XS + q * 2 + 1] = h1;
            Xl[r * XS + q * 2] = l0;     Xl[r * XS + q * 2 + 1] = l1;
        }
        for (int i = tid; i < NOUT * KP; i += 256) {
            int kp = i / NOUT, n = i % NOUT;
            float w0 = W[(size_t)(k0 + 2 * kp) * NOUT + n];
            float w1 = W[(size_t)(k0 + 2 * kp + 1) * NOUT + n];
            uint32_t h, l;
            split2(w0, w1, h, l);
            Wh[n * WS + kp] = h;
            Wl[n * WS + kp] = l;
        }
        __syncthreads();
#pragma unroll
        for (int s = 0; s < 2; s++) {
            int kb = s * 8 + (lane & 3);
            uint32_t ah[4], al[4];
            int arow = warp * 16 + (lane >> 2);
            ah[0] = Xh[arow * XS + kb];           al[0] = Xl[arow * XS + kb];
            ah[1] = Xh[(arow + 8) * XS + kb];     al[1] = Xl[(arow + 8) * XS + kb];
            ah[2] = Xh[arow * XS + kb + 4];       al[2] = Xl[arow * XS + kb + 4];
            ah[3] = Xh[(arow + 8) * XS + kb + 4]; al[3] = Xl[(arow + 8) * XS + kb + 4];
            int bn = lane >> 2;
#pragma unroll
            for (int nt = 0; nt < NT; nt++) {
                uint32_t bh[2], bl[2];
                int nb = (nt * 8 + bn) * WS;
                bh[0] = Wh[nb + kb]; bh[1] = Wh[nb + kb + 4];
                bl[0] = Wl[nb + kb]; bl[1] = Wl[nb + kb + 4];
                mma_bf16(acc[nt], ah, bh);
                mma_bf16(acc[nt], ah, bl);
                mma_bf16(acc[nt], al, bh);
            }
        }
        __syncthreads();
    }
    size_t row = m0 + warp * 16 + (lane >> 2);
    int col0 = (lane & 3) * 2;
#pragma unroll
    for (int nt = 0; nt < NT; nt++) {
        int c = nt * 8 + col0;
        float b0 = BIAS ? bias[c] : 0.0f, b1 = BIAS ? bias[c + 1] : 0.0f;
        float v0 = acc[nt][0] + b0, v1 = acc[nt][1] + b1;
        float v2 = acc[nt][2] + b0, v3 = acc[nt][3] + b1;
        if (RELU) {
            v0 = fmaxf(v0, 0.f); v1 = fmaxf(v1, 0.f);
            v2 = fmaxf(v2, 0.f); v3 = fmaxf(v3, 0.f);
        }
        *(float2*)&out[row * NOUT + c] = make_float2(v0, v1);
        *(float2*)&out[(row + 8) * NOUT + c] = make_float2(v2, v3);
    }
}

// ---------------- similarity via bf16x3 mma, full-K tile, single sync ------
// dynamic smem: 4 slabs of 128x36 uint32 (hi/lo for A and B), 72 KB total
__global__ void sim_mma_k() {
    constexpr int XS = 36;
    extern __shared__ uint32_t ssim[];
    uint32_t* Ah_s = ssim;
    uint32_t* Al_s = ssim + 128 * XS;
    uint32_t* Bh_s = ssim + 2 * 128 * XS;
    uint32_t* Bl_s = ssim + 3 * 128 * XS;
    int b = blockIdx.z;
    int i0 = blockIdx.y * 128, j0 = blockIdx.x * 128;
    const float* f1 = &g_feat[0][(size_t)(b * NPG + i0) * 64];
    const float* f2 = &g_feat[1][(size_t)(b * NPG + j0) * 64];
    int tid = threadIdx.x;
    int warp = tid >> 5, lane = tid & 31;
    int wm = warp >> 2, wn = warp & 3;
    float acc[4][4][4];
#pragma unroll
    for (int mt = 0; mt < 4; mt++)
#pragma unroll
        for (int nt = 0; nt < 4; nt++)
#pragma unroll
            for (int j = 0; j < 4; j++) acc[mt][nt][j] = 0.0f;

    // single load phase: full K=64 (16 float4 per row)
    for (int i = tid; i < 128 * 16; i += 256) {
        int r = i >> 4, q = i & 15;
        float4 va = *(const float4*)&f1[r * 64 + q * 4];
        float4 vb = *(const float4*)&f2[r * 64 + q * 4];
        uint32_t h0, l0, h1, l1;
        split2(va.x, va.y, h0, l0);
        split2(va.z, va.w, h1, l1);
        Ah_s[r * XS + q * 2] = h0;     Ah_s[r * XS + q * 2 + 1] = h1;
        Al_s[r * XS + q * 2] = l0;     Al_s[r * XS + q * 2 + 1] = l1;
        split2(vb.x, vb.y, h0, l0);
        split2(vb.z, vb.w, h1, l1);
        Bh_s[r * XS + q * 2] = h0;     Bh_s[r * XS + q * 2 + 1] = h1;
        Bl_s[r * XS + q * 2] = l0;     Bl_s[r * XS + q * 2 + 1] = l1;
    }
    __syncthreads();

#pragma unroll
    for (int s = 0; s < 4; s++) {
        int kb = s * 8 + (lane & 3);
        uint32_t ah[4][4], al[4][4], bh[4][2], bl[4][2];
#pragma unroll
        for (int mt = 0; mt < 4; mt++) {
            int arow = wm * 64 + mt * 16 + (lane >> 2);
            ah[mt][0] = Ah_s[arow * XS + kb];
            ah[mt][1] = Ah_s[(arow + 8) * XS + kb];
            ah[mt][2] = Ah_s[arow * XS + kb + 4];
            ah[mt][3] = Ah_s[(arow + 8) * XS + kb + 4];
            al[mt][0] = Al_s[arow * XS + kb];
            al[mt][1] = Al_s[(arow + 8) * XS + kb];
            al[mt][2] = Al_s[arow * XS + kb + 4];
            al[mt][3] = Al_s[(arow + 8) * XS + kb + 4];
        }
#pragma unroll
        for (int nt = 0; nt < 4; nt++) {
            int bnode = wn * 32 + nt * 8 + (lane >> 2);
            bh[nt][0] = Bh_s[bnode * XS + kb];
            bh[nt][1] = Bh_s[bnode * XS + kb + 4];
            bl[nt][0] = Bl_s[bnode * XS + kb];
            bl[nt][1] = Bl_s[bnode * XS + kb + 4];
        }
#pragma unroll
        for (int mt = 0; mt < 4; mt++)
#pragma unroll
            for (int nt = 0; nt < 4; nt++) {
                mma_bf16(acc[mt][nt], ah[mt], bh[nt]);
                mma_bf16(acc[mt][nt], ah[mt], bl[nt]);
                mma_bf16(acc[mt][nt], al[mt], bh[nt]);
            }
    }

    float lmin = FLT_MAX, lmax = -FLT_MAX;
    __half* sp = &g_simh[(size_t)b * NPG * NPG];
    int col0 = (lane & 3) * 2;
#pragma unroll
    for (int mt = 0; mt < 4; mt++) {
        size_t r0 = (size_t)(i0 + wm * 64 + mt * 16 + (lane >> 2));
#pragma unroll
        for (int nt = 0; nt < 4; nt++) {
            int c = j0 + wn * 32 + nt * 8 + col0;
            float v0 = acc[mt][nt][0], v1 = acc[mt][nt][1];
            float v2 = acc[mt][nt][2], v3 = acc[mt][nt][3];
            lmin = fminf(lmin, fminf(fminf(v0, v1), fminf(v2, v3)));
            lmax = fmaxf(lmax, fmaxf(fmaxf(v0, v1), fmaxf(v2, v3)));
            *(__half2*)&sp[r0 * NPG + c] = __floats2half2_rn(v0, v1);
            *(__half2*)&sp[(r0 + 8) * NPG + c] = __floats2half2_rn(v2, v3);
        }
    }
    __shared__ float rmin[256], rmax[256];
    rmin[tid] = lmin;
    rmax[tid] = lmax;
    __syncthreads();
    for (int s = 128; s > 0; s >>= 1) {
        if (tid < s) {
            rmin[tid] = fminf(rmin[tid], rmin[tid + s]);
            rmax[tid] = fmaxf(rmax[tid], rmax[tid + s]);
        }
        __syncthreads();
    }
    if (tid == 0) {
        atomicMinFloat(&g_smin[b], rmin[0]);
        atomicMaxFloat(&g_smax[b], rmax[0]);
    }
}

// ---------------- histogram (threshold CDF, half2) + final head fused ------
__global__ void hist_final_k(const float* __restrict__ Wt, const float* __restrict__ Wtb,
                             const float* __restrict__ tb, const float* __restrict__ W1,
                             const float* __restrict__ b1, const float* __restrict__ Ws,
                             const float* __restrict__ bs, float* __restrict__ out) {
    int b = blockIdx.x;
    int t = threadIdx.x;
    int lane = t & 31, warp = t >> 5;     // 32 warps
    __shared__ __half2 thr_s[15];
    if (t < 15) {
        float vmin = sigmoidf_(g_smin[b]);
        float vmax = sigmoidf_(g_smax[b]);
        float width = (vmax - vmin) * (1.0f / D_BINS);
        float thr;
        if (width > 0.0f) {
            float bnd = vmin + (float)(t + 1) * width;
            thr = logf(bnd / (1.0f - bnd));
        } else {
            thr = FLT_MAX;
        }
        thr_s[t] = __float2half2_rn(thr);
    }
    __syncthreads();
    __half2 T2[15];
#pragma unroll
    for (int k = 0; k < 15; k++) T2[k] = thr_s[k];

    const uint4* qp = (const uint4*)&g_simh[(size_t)b * NPG * NPG];
    __half2 C2[15];
#pragma unroll
    for (int k = 0; k < 15; k++) C2[k] = __float2half2_rn(0.0f);
    for (int i = t; i < 32768; i += 1024) {
        uint4 q = qp[i];
        __half2 h0 = *(__half2*)&q.x;
        __half2 h1 = *(__half2*)&q.y;
        __half2 h2 = *(__half2*)&q.z;
        __half2 h3 = *(__half2*)&q.w;
#pragma unroll
        for (int k = 0; k < 15; k++) {
            C2[k] = __hadd2(C2[k], __hge2(h0, T2[k]));
            C2[k] = __hadd2(C2[k], __hge2(h1, T2[k]));
            C2[k] = __hadd2(C2[k], __hge2(h2, T2[k]));
            C2[k] = __hadd2(C2[k], __hge2(h3, T2[k]));
        }
    }
    __shared__ int red[32][16];
#pragma unroll
    for (int k = 0; k < 15; k++) {
        int c = (int)(__low2float(C2[k]) + __high2float(C2[k]));
#pragma unroll
        for (int o = 16; o; o >>= 1) c += __shfl_xor_sync(0xffffffffu, c, o);
        if (lane == 0) red[warp][k] = c;
    }
    __syncthreads();
    __shared__ int cdf_s[15];
    if (t < 15) {
        int s = 0;
#pragma unroll
        for (int w = 0; w < 32; w++) s += red[w][t];
        cdf_s[t] = s;
    }

    // ---- final head ----
    __shared__ float p1s[64], p2s[64];
    __shared__ float scp[64 * 16];
    __shared__ float feat[32];
    __shared__ float hs[32];
    if (t < 64) {
        p1s[t] = g_pool[0][b * 64 + t];
        p2s[t] = g_pool[1][b * 64 + t];
    }
    __syncthreads();
    if (t < 64) {
        float s[16];
#pragma unroll
        for (int k = 0; k < 16; k++) s[k] = 0.0f;
        for (int j = 0; j < 64; j++) {
            float pj = p2s[j];
            const float* wp = &Wt[(size_t)(t * 64 + j) * 16];
#pragma unroll
            for (int k = 0; k < 16; k++) s[k] += wp[k] * pj;
        }
        float p1v = p1s[t];
#pragma unroll
        for (int k = 0; k < 16; k++) scp[t * 16 + k] = p1v * s[k];
    }
    __syncthreads();
    if (t < 16) {
        float acc = tb[t];
        for (int i = 0; i < 64; i++) acc += scp[i * 16 + t];
        float blk = 0.0f;
        for (int i = 0; i < 64; i++) blk += Wtb[t * 128 + i] * p1s[i];
        for (int i = 0; i < 64; i++) blk += Wtb[t * 128 + 64 + i] * p2s[i];
        float tv = acc + blk;
        feat[t] = fmaxf(tv, 0.0f);
        int C_lo = (t == 0) ? NPG * NPG : cdf_s[t - 1];
        int C_hi = (t == 15) ? 0 : cdf_s[t];
        feat[16 + t] = (float)(C_lo - C_hi) * (1.0f / ((float)NPG * (float)NPG));
    }
    __syncthreads();
    if (t < 32) {
        float acc = b1[t];
        for (int i = 0; i < 32; i++) acc += feat[i] * W1[i * 32 + t];
        hs[t] = fmaxf(acc, 0.0f);
    }
    __syncthreads();
    if (t == 0) {
        float acc = bs[0];
        for (int j = 0; j < 32; j++) acc += hs[j] * Ws[j];
        out[b] = sigmoidf_(acc);
    }
}

// ---------------- launcher ----------------
extern "C" void kernel_launch(void* const* d_in, const int* in_sizes, int n_in,
                              void* d_out, int out_size) {
    const float* x1  = (const float*)d_in[0];
    const float* x2  = (const float*)d_in[1];
    const int* ei1   = (const int*)d_in[2];
    const int* ei2   = (const int*)d_in[3];
    const float* Wc1 = (const float*)d_in[6];
    const float* bc1 = (const float*)d_in[7];
    const float* Wc2 = (const float*)d_in[8];
    const float* bc2 = (const float*)d_in[9];
    const float* Wc3 = (const float*)d_in[10];
    const float* bc3 = (const float*)d_in[11];
    const float* Watt = (const float*)d_in[12];
    const float* Wt  = (const float*)d_in[13];
    const float* Wtb = (const float*)d_in[14];
    const float* tb  = (const float*)d_in[15];
    const float* W1  = (const float*)d_in[16];
    const float* b1  = (const float*)d_in[17];
    const float* Ws  = (const float*)d_in[18];
    const float* bs  = (const float*)d_in[19];
    float* out = (float*)d_out;

    void* p;
    float *a0, *a1, *b0, *b1p, *f0, *f1;
    cudaGetSymbolAddress(&p, g_bufA);
    a0 = (float*)p; a1 = a0 + (size_t)NTOT * D_F1;
    cudaGetSymbolAddress(&p, g_bufB);
    b0 = (float*)p; b1p = b0 + (size_t)NTOT * D_F1;
    cudaGetSymbolAddress(&p, g_feat);
    f0 = (float*)p; f1 = f0 + (size_t)NTOT * D_F3;

    // opt-in large dynamic smem (idempotent)
    cudaFuncSetAttribute(agg_pool_k, cudaFuncAttributeMaxDynamicSharedMemorySize,
                         NPG * D_F3 * 4);
    cudaFuncSetAttribute(sim_mma_k, cudaFuncAttributeMaxDynamicSharedMemorySize,
                         4 * 128 * 36 * 4);

    init_k<<<NTOT / 256, 256>>>();

    // CSR build for BOTH sides (batched over grid.y)
    deg_k<<<dim3(NEDGE / 256, 2), 256>>>(ei1 + NEDGE, ei2 + NEDGE);
    scanA_k<<<dim3(256, 2), 256>>>();
    scanC_k<<<dim3(256, 2), 256>>>();
    scatter_k<<<dim3(NEDGE / 256, 2), 256>>>(ei1, ei2);

    // conv pipeline
    agg_k<32, false, false><<<dim3(NB, 2), 1024>>>(x1, x2, nullptr, a0, a1);
    gemm_mma_k<32, 128, true, true><<<dim3(NTOT / 128, 2), 256>>>(a0, a1, Wc1, bc1, b0, b1p);

    gemm_mma_k<128, 96, false, false><<<dim3(NTOT / 128, 2), 256>>>(b0, b1p, Wc2, nullptr, a0, a1);
    agg_k<96, true, true><<<dim3(NB, 2), 1024>>>(a0, a1, bc2, b0, b1p);

    gemm_mma_k<96, 64, false, false><<<dim3(NTOT / 128, 2), 256>>>(b0, b1p, Wc3, nullptr, a0, a1);
    agg_pool_k<<<dim3(NB, 2), 1024, NPG * D_F3 * 4>>>(a0, a1, bc3, f0, f1, Watt);

    sim_mma_k<<<dim3(4, 4, NB), 256, 4 * 128 * 36 * 4>>>();
    hist_final_k<<<NB, 1024>>>(Wt, Wtb, tb, W1, b1, Ws, bs, out);
}

// round 15
// speedup vs baseline: 1.1449x; 1.1449x over previous
#include <cuda_runtime.h>
#include <cuda_fp16.h>
#include <math.h>
#include <cfloat>
#include <stdint.h>

// ---------------- problem dims (fixed) ----------------
#define NTOT  65536      // nodes per side (B*N)
#define NEDGE 524288     // edges per side
#define NB    128        // graphs
#define NPG   512        // nodes per graph
#define D_F1  128
#define D_F2  96
#define D_F3  64
#define D_BINS 16

// ---------------- device scratch (per-side slabs for batched launches) -----
__device__ float g_bufA[2][NTOT * D_F1];
__device__ float g_bufB[2][NTOT * D_F1];
__device__ float g_feat[2][NTOT * D_F3];
__device__ float g_dinv[2][NTOT];
__device__ int   g_degi[2][NTOT];
__device__ int   g_row[2][NTOT + 1];
__device__ int   g_cursor[2][NTOT];
__device__ int   g_bsum[2][256];
__device__ int2  g_epack[2][NEDGE];                  // {src, norm bits}
__device__ __half g_simh[(size_t)NB * NPG * NPG];   // fp16 similarity scores
__device__ float g_smin[NB];
__device__ float g_smax[NB];
__device__ float g_pool[2][NB * D_F3];

__device__ __forceinline__ float sigmoidf_(float x) { return 1.0f / (1.0f + expf(-x)); }

__device__ __forceinline__ void atomicMinFloat(float* addr, float val) {
    int old = __float_as_int(*addr);
    while (__int_as_float(old) > val) {
        int assumed = old;
        old = atomicCAS((int*)addr, assumed, __float_as_int(val));
        if (old == assumed) break;
    }
}
__device__ __forceinline__ void atomicMaxFloat(float* addr, float val) {
    int old = __float_as_int(*addr);
    while (__int_as_float(old) < val) {
        int assumed = old;
        old = atomicCAS((int*)addr, assumed, __float_as_int(val));
        if (old == assumed) break;
    }
}

// ---------------- bf16x3 helpers (fp32 emulation via bf16 split) -----------
__device__ __forceinline__ void split2(float x0, float x1, uint32_t& h, uint32_t& l) {
    asm("cvt.rn.bf16x2.f32 %0, %1, %2;" : "=r"(h) : "f"(x1), "f"(x0));
    float r0 = x0 - __uint_as_float(h << 16);
    float r1 = x1 - __uint_as_float(h & 0xffff0000u);
    asm("cvt.rn.bf16x2.f32 %0, %1, %2;" : "=r"(l) : "f"(r1), "f"(r0));
}
__device__ __forceinline__ void mma_bf16(float* d, const uint32_t* a, const uint32_t* b) {
    asm volatile(
        "mma.sync.aligned.m16n8k16.row.col.f32.bf16.bf16.f32 "
        "{%0,%1,%2,%3}, {%4,%5,%6,%7}, {%8,%9}, {%0,%1,%2,%3};\n"
        : "+f"(d[0]), "+f"(d[1]), "+f"(d[2]), "+f"(d[3])
        : "r"(a[0]), "r"(a[1]), "r"(a[2]), "r"(a[3]), "r"(b[0]), "r"(b[1]));
}

// block-wide exclusive scan of 256 ints (one value per thread)
__device__ __forceinline__ int block_exscan_256(int v, int* sm8) {
    int lane = threadIdx.x & 31, w = threadIdx.x >> 5;
    int x = v;
#pragma unroll
    for (int o = 1; o < 32; o <<= 1) {
        int y = __shfl_up_sync(0xffffffffu, x, o);
        if (lane >= o) x += y;
    }
    if (lane == 31) sm8[w] = x;
    __syncthreads();
    if (threadIdx.x < 8) {
        int s = sm8[threadIdx.x];
#pragma unroll
        for (int o = 1; o < 8; o <<= 1) {
            int y = __shfl_up_sync(0xffu, s, o);
            if ((int)threadIdx.x >= o) s += y;
        }
        sm8[threadIdx.x] = s;
    }
    __syncthreads();
    int woff = w ? sm8[w - 1] : 0;
    return woff + x - v;
}

// ---------------- init ----------------
__global__ void init_k() {
    int i = blockIdx.x * blockDim.x + threadIdx.x;
    if (i < NTOT) { g_degi[0][i] = 0; g_degi[1][i] = 0; }
    if (i < NB) { g_smin[i] = FLT_MAX; g_smax[i] = -FLT_MAX; }
}

// ---------------- degree (both sides via grid.y) ----------------
__global__ void deg_k(const int* __restrict__ dst0, const int* __restrict__ dst1) {
    int side = blockIdx.y;
    const int* dst = side ? dst1 : dst0;
    int e = blockIdx.x * blockDim.x + threadIdx.x;
    if (e < NEDGE) atomicAdd(&g_degi[side][dst[e]], 1);
}

// ---------------- 2-phase parallel scan (A computes dinv + block sums) -----
__global__ void scanA_k() {
    int side = blockIdx.y;
    int i = blockIdx.x * 256 + threadIdx.x;
    int v = g_degi[side][i];
    g_dinv[side][i] = rsqrtf((float)v + 1.0f);
#pragma unroll
    for (int o = 16; o; o >>= 1) v += __shfl_xor_sync(0xffffffffu, v, o);
    __shared__ int sm[8];
    if ((threadIdx.x & 31) == 0) sm[threadIdx.x >> 5] = v;
    __syncthreads();
    if (threadIdx.x == 0) {
        int s = 0;
#pragma unroll
        for (int j = 0; j < 8; j++) s += sm[j];
        g_bsum[side][blockIdx.x] = s;
    }
}
__global__ void scanC_k() {
    int side = blockIdx.y;
    int bid = blockIdx.x;
    int t = threadIdx.x;
    int lane = t & 31, w = t >> 5;
    int pv = (t < bid) ? g_bsum[side][t] : 0;
#pragma unroll
    for (int o = 16; o; o >>= 1) pv += __shfl_xor_sync(0xffffffffu, pv, o);
    __shared__ int rsm[8];
    if (lane == 0) rsm[w] = pv;
    __syncthreads();
    __shared__ int prefix_s;
    if (t == 0) {
        int s = 0;
#pragma unroll
        for (int j = 0; j < 8; j++) s += rsm[j];
        prefix_s = s;
    }
    __syncthreads();
    int prefix = prefix_s;
    int i = bid * 256 + t;
    int d = g_degi[side][i];
    __shared__ int sm[8];
    int ex = block_exscan_256(d, sm);
    int off = prefix + ex;
    g_row[side][i] = off;
    g_cursor[side][i] = off;
    if (i == NTOT - 1) g_row[side][NTOT] = NEDGE;
}

// ---------------- scatter edges into CSR order (packed src+norm) -----------
__global__ void scatter_k(const int* __restrict__ ei0, const int* __restrict__ ei1) {
    int side = blockIdx.y;
    const int* ei = side ? ei1 : ei0;
    const int* src = ei;
    const int* dst = ei + NEDGE;
    int e = blockIdx.x * blockDim.x + threadIdx.x;
    if (e >= NEDGE) return;
    int s = src[e], d = dst[e];
    int pos = atomicAdd(&g_cursor[side][d], 1);
    float nm = g_dinv[side][s] * g_dinv[side][d];
    g_epack[side][pos] = make_int2(s, __float_as_int(nm));
}

// ---------------- graph-per-block aggregation (L1-resident gathers) --------
// CW = chunks handled per block (channel split via grid.z for big layers)
template <int OUT, int CW, bool BIAS, bool RELU>
__global__ void agg_k(const float* __restrict__ xw0, const float* __restrict__ xw1,
                      const float* __restrict__ bias,
                      float* __restrict__ out0, float* __restrict__ out1) {
    constexpr int C4 = OUT / 4;
    int side = blockIdx.y;
    int coff = blockIdx.z * CW;
    const float* xw = side ? xw1 : xw0;
    float* out = side ? out1 : out0;
    int base = blockIdx.x * NPG;
    const float4* xw4 = (const float4*)xw;
    float4* out4 = (float4*)out;
    for (int wi = threadIdx.x; wi < NPG * CW; wi += blockDim.x) {
        int node = base + wi / CW;
        int chunk = coff + wi % CW;
        float dv = g_dinv[side][node];
        float dv2 = dv * dv;
        float4 v = xw4[(size_t)node * C4 + chunk];
        float4 acc = make_float4(v.x * dv2, v.y * dv2, v.z * dv2, v.w * dv2);
        int beg = g_row[side][node], end = g_row[side][node + 1];
        for (int e = beg; e < end; e++) {
            int2 ep = g_epack[side][e];
            float nm = __int_as_float(ep.y);
            float4 u = xw4[(size_t)ep.x * C4 + chunk];
            acc.x += u.x * nm; acc.y += u.y * nm; acc.z += u.z * nm; acc.w += u.w * nm;
        }
        if (BIAS) {
            acc.x += bias[chunk * 4 + 0];
            acc.y += bias[chunk * 4 + 1];
            acc.z += bias[chunk * 4 + 2];
            acc.w += bias[chunk * 4 + 3];
        }
        if (RELU) {
            acc.x = fmaxf(acc.x, 0.f); acc.y = fmaxf(acc.y, 0.f);
            acc.z = fmaxf(acc.z, 0.f); acc.w = fmaxf(acc.w, 0.f);
        }
        out4[(size_t)node * C4 + chunk] = acc;
    }
}

// ---------------- agg3 + attention pool fused (one block per graph) --------
__global__ void agg_pool_k(const float* __restrict__ xw0, const float* __restrict__ xw1,
                           const float* __restrict__ bias,
                           float* __restrict__ out0, float* __restrict__ out1,
                           const float* __restrict__ Watt) {
    constexpr int C4 = 16;
    extern __shared__ float sfeat[];       // NPG*64 floats = 128 KB
    int side = blockIdx.y;
    int b = blockIdx.x;
    const float* xw = side ? xw1 : xw0;
    float* out = side ? out1 : out0;
    int base = b * NPG;
    const float4* xw4 = (const float4*)xw;
    float4* out4 = (float4*)out;
    float4* sf4 = (float4*)sfeat;
    int t = threadIdx.x;                    // 1024

    // ---- aggregation ----
    for (int wi = t; wi < NPG * C4; wi += 1024) {
        int node = base + wi / C4;
        int chunk = wi % C4;
        float dv = g_dinv[side][node];
        float dv2 = dv * dv;
        float4 v = xw4[(size_t)node * C4 + chunk];
        float4 acc = make_float4(v.x * dv2, v.y * dv2, v.z * dv2, v.w * dv2);
        int beg = g_row[side][node], end = g_row[side][node + 1];
        for (int e = beg; e < end; e++) {
            int2 ep = g_epack[side][e];
            float nm = __int_as_float(ep.y);
            float4 u = xw4[(size_t)ep.x * C4 + chunk];
            acc.x += u.x * nm; acc.y += u.y * nm; acc.z += u.z * nm; acc.w += u.w * nm;
        }
        acc.x += bias[chunk * 4 + 0];
        acc.y += bias[chunk * 4 + 1];
        acc.z += bias[chunk * 4 + 2];
        acc.w += bias[chunk * 4 + 3];
        out4[(size_t)node * C4 + chunk] = acc;
        sf4[wi] = acc;
    }
    __syncthreads();

    // ---- attention pooling on the smem slab ----
    __shared__ float p16[16][64];
    __shared__ float meanc[64];
    __shared__ float ctx[64];
    __shared__ float wsum[32][64];
    int d = t & 63, g = t >> 6;
    float loc = 0.0f;
    for (int r = g; r < NPG; r += 16) loc += sfeat[r * 64 + d];
    p16[g][d] = loc;
    __syncthreads();
    if (t < 64) {
        float s = 0.0f;
#pragma unroll
        for (int j = 0; j < 16; j++) s += p16[j][t];
        meanc[t] = s * (1.0f / NPG);
    }
    __syncthreads();
    if (t < 64) {
        float c = 0.0f;
        for (int i = 0; i < 64; i++) c += meanc[i] * Watt[i * 64 + t];
        ctx[t] = tanhf(c);
    }
    __syncthreads();
    int w = t >> 5, l = t & 31;
    float a0 = 0.0f, a1 = 0.0f;
    float c0 = ctx[l], c1 = ctx[l + 32];
    for (int r = w * 16; r < w * 16 + 16; r++) {
        float v0 = sfeat[r * 64 + l], v1 = sfeat[r * 64 + 32 + l];
        float dp = v0 * c0 + v1 * c1;
#pragma unroll
        for (int o = 16; o; o >>= 1) dp += __shfl_xor_sync(0xffffffffu, dp, o);
        float coef = sigmoidf_(dp);
        a0 += v0 * coef;
        a1 += v1 * coef;
    }
    wsum[w][l] = a0;
    wsum[w][l + 32] = a1;
    __syncthreads();
    if (t < 64) {
        float s = 0.0f;
#pragma unroll
        for (int w2 = 0; w2 < 32; w2++) s += wsum[w2][t];
        g_pool[side][b * 64 + t] = s;
    }
}

// ---------------- bf16x3 tensor-core GEMM (both sides via grid.y) ----------
template <int KIN, int NOUT, bool BIAS, bool RELU>
__global__ void gemm_mma_k(const float* __restrict__ x0, const float* __restrict__ x1,
                           const float* __restrict__ W, const float* __restrict__ bias,
                           float* __restrict__ out0, float* __restrict__ out1) {
    constexpr int KC = 32;
    constexpr int KP = KC / 2;
    constexpr int NT = NOUT / 8;
    constexpr int XS = 20;
    constexpr int WS = 20;
    __shared__ uint32_t Xh[128 * XS];
    __shared__ uint32_t Xl[128 * XS];
    __shared__ uint32_t Wh[NOUT * WS];
    __shared__ uint32_t Wl[NOUT * WS];
    int side = blockIdx.y;
    const float* x = side ? x1 : x0;
    float* out = side ? out1 : out0;
    int tid = threadIdx.x;
    int warp = tid >> 5, lane = tid & 31;
    size_t m0 = (size_t)blockIdx.x * 128;
    float acc[NT][4];
#pragma unroll
    for (int i = 0; i < NT; i++)
#pragma unroll
        for (int j = 0; j < 4; j++) acc[i][j] = 0.0f;

    for (int k0 = 0; k0 < KIN; k0 += KC) {
        for (int i = tid; i < 128 * 8; i += 256) {
            int r = i >> 3, q = i & 7;
            float4 v = *(const float4*)&x[(m0 + r) * KIN + k0 + q * 4];
            uint32_t h0, l0, h1, l1;
            split2(v.x, v.y, h0, l0);
            split2(v.z, v.w, h1, l1);
            Xh[r * XS + q * 2] = h0;     Xh[r * XS + q * 2 + 1] = h1;
            Xl[r * XS + q * 2] = l0;     Xl[r * XS + q * 2 + 1] = l1;
        }
        for (int i = tid; i < NOUT * KP; i += 256) {
            int kp = i / NOUT, n = i % NOUT;
            float w0 = W[(size_t)(k0 + 2 * kp) * NOUT + n];
            float w1 = W[(size_t)(k0 + 2 * kp + 1) * NOUT + n];
            uint32_t h, l;
            split2(w0, w1, h, l);
            Wh[n * WS + kp] = h;
            Wl[n * WS + kp] = l;
        }
        __syncthreads();
#pragma unroll
        for (int s = 0; s < 2; s++) {
            int kb = s * 8 + (lane & 3);
            uint32_t ah[4], al[4];
            int arow = warp * 16 + (lane >> 2);
            ah[0] = Xh[arow * XS + kb];           al[0] = Xl[arow * XS + kb];
            ah[1] = Xh[(arow + 8) * XS + kb];     al[1] = Xl[(arow + 8) * XS + kb];
            ah[2] = Xh[arow * XS + kb + 4];       al[2] = Xl[arow * XS + kb + 4];
            ah[3] = Xh[(arow + 8) * XS + kb + 4]; al[3] = Xl[(arow + 8) * XS + kb + 4];
            int bn = lane >> 2;
#pragma unroll
            for (int nt = 0; nt < NT; nt++) {
                uint32_t bh[2], bl[2];
                int nb = (nt * 8 + bn) * WS;
                bh[0] = Wh[nb + kb]; bh[1] = Wh[nb + kb + 4];
                bl[0] = Wl[nb + kb]; bl[1] = Wl[nb + kb + 4];
                mma_bf16(acc[nt], ah, bh);
                mma_bf16(acc[nt], ah, bl);
                mma_bf16(acc[nt], al, bh);
            }
        }
        __syncthreads();
    }
    size_t row = m0 + warp * 16 + (lane >> 2);
    int col0 = (lane & 3) * 2;
#pragma unroll
    for (int nt = 0; nt < NT; nt++) {
        int c = nt * 8 + col0;
        float b0 = BIAS ? bias[c] : 0.0f, b1 = BIAS ? bias[c + 1] : 0.0f;
        float v0 = acc[nt][0] + b0, v1 = acc[nt][1] + b1;
        float v2 = acc[nt][2] + b0, v3 = acc[nt][3] + b1;
        if (RELU) {
            v0 = fmaxf(v0, 0.f); v1 = fmaxf(v1, 0.f);
            v2 = fmaxf(v2, 0.f); v3 = fmaxf(v3, 0.f);
        }
        *(float2*)&out[row * NOUT + c] = make_float2(v0, v1);
        *(float2*)&out[(row + 8) * NOUT + c] = make_float2(v2, v3);
    }
}

// ---------------- similarity via bf16x3 mma, 128x128 tile, fp16 store ------
__global__ void sim_mma_k() {
    constexpr int XS = 20;
    int b = blockIdx.z;
    int i0 = blockIdx.y * 128, j0 = blockIdx.x * 128;
    __shared__ uint32_t Ah_s[128 * XS];
    __shared__ uint32_t Al_s[128 * XS];
    __shared__ uint32_t Bh_s[128 * XS];
    __shared__ uint32_t Bl_s[128 * XS];
    const float* f1 = &g_feat[0][(size_t)(b * NPG + i0) * 64];
    const float* f2 = &g_feat[1][(size_t)(b * NPG + j0) * 64];
    int tid = threadIdx.x;
    int warp = tid >> 5, lane = tid & 31;
    int wm = warp >> 2, wn = warp & 3;
    float acc[4][4][4];
#pragma unroll
    for (int mt = 0; mt < 4; mt++)
#pragma unroll
        for (int nt = 0; nt < 4; nt++)
#pragma unroll
            for (int j = 0; j < 4; j++) acc[mt][nt][j] = 0.0f;

    for (int k0 = 0; k0 < 64; k0 += 32) {
        for (int i = tid; i < 128 * 8; i += 256) {
            int r = i >> 3, q = i & 7;
            float4 va = *(const float4*)&f1[r * 64 + k0 + q * 4];
            float4 vb = *(const float4*)&f2[r * 64 + k0 + q * 4];
            uint32_t h0, l0, h1, l1;
            split2(va.x, va.y, h0, l0);
            split2(va.z, va.w, h1, l1);
            Ah_s[r * XS + q * 2] = h0;     Ah_s[r * XS + q * 2 + 1] = h1;
            Al_s[r * XS + q * 2] = l0;     Al_s[r * XS + q * 2 + 1] = l1;
            split2(vb.x, vb.y, h0, l0);
            split2(vb.z, vb.w, h1, l1);
            Bh_s[r * XS + q * 2] = h0;     Bh_s[r * XS + q * 2 + 1] = h1;
            Bl_s[r * XS + q * 2] = l0;     Bl_s[r * XS + q * 2 + 1] = l1;
        }
        __syncthreads();
#pragma unroll
        for (int s = 0; s < 2; s++) {
            int kb = s * 8 + (lane & 3);
            uint32_t ah[4][4], al[4][4], bh[4][2], bl[4][2];
#pragma unroll
            for (int mt = 0; mt < 4; mt++) {
                int arow = wm * 64 + mt * 16 + (lane >> 2);
                ah[mt][0] = Ah_s[arow * XS + kb];
                ah[mt][1] = Ah_s[(arow + 8) * XS + kb];
                ah[mt][2] = Ah_s[arow * XS + kb + 4];
                ah[mt][3] = Ah_s[(arow + 8) * XS + kb + 4];
                al[mt][0] = Al_s[arow * XS + kb];
                al[mt][1] = Al_s[(arow + 8) * XS + kb];
                al[mt][2] = Al_s[arow * XS + kb + 4];
                al[mt][3] = Al_s[(arow + 8) * XS + kb + 4];
            }
#pragma unroll
            for (int nt = 0; nt < 4; nt++) {
                int bnode = wn * 32 + nt * 8 + (lane >> 2);
                bh[nt][0] = Bh_s[bnode * XS + kb];
                bh[nt][1] = Bh_s[bnode * XS + kb + 4];
                bl[nt][0] = Bl_s[bnode * XS + kb];
                bl[nt][1] = Bl_s[bnode * XS + kb + 4];
            }
#pragma unroll
            for (int mt = 0; mt < 4; mt++)
#pragma unroll
                for (int nt = 0; nt < 4; nt++) {
                    mma_bf16(acc[mt][nt], ah[mt], bh[nt]);
                    mma_bf16(acc[mt][nt], ah[mt], bl[nt]);
                    mma_bf16(acc[mt][nt], al[mt], bh[nt]);
                }
        }
        __syncthreads();
    }
    float lmin = FLT_MAX, lmax = -FLT_MAX;
    __half* sp = &g_simh[(size_t)b * NPG * NPG];
    int col0 = (lane & 3) * 2;
#pragma unroll
    for (int mt = 0; mt < 4; mt++) {
        size_t r0 = (size_t)(i0 + wm * 64 + mt * 16 + (lane >> 2));
#pragma unroll
        for (int nt = 0; nt < 4; nt++) {
            int c = j0 + wn * 32 + nt * 8 + col0;
            float v0 = acc[mt][nt][0], v1 = acc[mt][nt][1];
            float v2 = acc[mt][nt][2], v3 = acc[mt][nt][3];
            lmin = fminf(lmin, fminf(fminf(v0, v1), fminf(v2, v3)));
            lmax = fmaxf(lmax, fmaxf(fmaxf(v0, v1), fmaxf(v2, v3)));
            *(__half2*)&sp[r0 * NPG + c] = __floats2half2_rn(v0, v1);
            *(__half2*)&sp[(r0 + 8) * NPG + c] = __floats2half2_rn(v2, v3);
        }
    }
    __shared__ float rmin[256], rmax[256];
    rmin[tid] = lmin;
    rmax[tid] = lmax;
    __syncthreads();
    for (int s = 128; s > 0; s >>= 1) {
        if (tid < s) {
            rmin[tid] = fminf(rmin[tid], rmin[tid + s]);
            rmax[tid] = fmaxf(rmax[tid], rmax[tid + s]);
        }
        __syncthreads();
    }
    if (tid == 0) {
        atomicMinFloat(&g_smin[b], rmin[0]);
        atomicMaxFloat(&g_smax[b], rmax[0]);
    }
}

// ---------------- histogram (threshold CDF, half2, 2-way ILP) + head -------
__global__ void hist_final_k(const float* __restrict__ Wt, const float* __restrict__ Wtb,
                             const float* __restrict__ tb, const float* __restrict__ W1,
                             const float* __restrict__ b1, const float* __restrict__ Ws,
                             const float* __restrict__ bs, float* __restrict__ out) {
    int b = blockIdx.x;
    int t = threadIdx.x;
    int lane = t & 31, warp = t >> 5;     // 32 warps
    __shared__ __half2 thr_s[15];
    if (t < 15) {
        float vmin = sigmoidf_(g_smin[b]);
        float vmax = sigmoidf_(g_smax[b]);
        float width = (vmax - vmin) * (1.0f / D_BINS);
        float thr;
        if (width > 0.0f) {
            float bnd = vmin + (float)(t + 1) * width;
            thr = logf(bnd / (1.0f - bnd));
        } else {
            thr = FLT_MAX;
        }
        thr_s[t] = __float2half2_rn(thr);
    }
    __syncthreads();
    __half2 T2[15];
#pragma unroll
    for (int k = 0; k < 15; k++) T2[k] = thr_s[k];

    const uint4* qp = (const uint4*)&g_simh[(size_t)b * NPG * NPG];
    __half2 C2[15];
#pragma unroll
    for (int k = 0; k < 15; k++) C2[k] = __float2half2_rn(0.0f);
    // two independent streams of 16384 uint4 each; per-half count <= 128 (exact fp16)
    for (int i = t; i < 16384; i += 1024) {
        uint4 qa = qp[i];
        uint4 qb = qp[i + 16384];
        __half2 a0 = *(__half2*)&qa.x, a1 = *(__half2*)&qa.y;
        __half2 a2 = *(__half2*)&qa.z, a3 = *(__half2*)&qa.w;
        __half2 b0 = *(__half2*)&qb.x, b1h = *(__half2*)&qb.y;
        __half2 b2 = *(__half2*)&qb.z, b3 = *(__half2*)&qb.w;
#pragma unroll
        for (int k = 0; k < 15; k++) {
            C2[k] = __hadd2(C2[k], __hge2(a0, T2[k]));
            C2[k] = __hadd2(C2[k], __hge2(a1, T2[k]));
            C2[k] = __hadd2(C2[k], __hge2(a2, T2[k]));
            C2[k] = __hadd2(C2[k], __hge2(a3, T2[k]));
            C2[k] = __hadd2(C2[k], __hge2(b0, T2[k]));
            C2[k] = __hadd2(C2[k], __hge2(b1h, T2[k]));
            C2[k] = __hadd2(C2[k], __hge2(b2, T2[k]));
            C2[k] = __hadd2(C2[k], __hge2(b3, T2[k]));
        }
    }
    __shared__ int red[32][16];
#pragma unroll
    for (int k = 0; k < 15; k++) {
        int c = (int)(__low2float(C2[k]) + __high2float(C2[k]));
#pragma unroll
        for (int o = 16; o; o >>= 1) c += __shfl_xor_sync(0xffffffffu, c, o);
        if (lane == 0) red[warp][k] = c;
    }
    __syncthreads();
    __shared__ int cdf_s[15];
    if (t < 15) {
        int s = 0;
#pragma unroll
        for (int w = 0; w < 32; w++) s += red[w][t];
        cdf_s[t] = s;
    }

    // ---- final head ----
    __shared__ float p1s[64], p2s[64];
    __shared__ float scp[64 * 16];
    __shared__ float feat[32];
    __shared__ float hs[32];
    if (t < 64) {
        p1s[t] = g_pool[0][b * 64 + t];
        p2s[t] = g_pool[1][b * 64 + t];
    }
    __syncthreads();
    if (t < 64) {
        float s[16];
#pragma unroll
        for (int k = 0; k < 16; k++) s[k] = 0.0f;
        for (int j = 0; j < 64; j++) {
            float pj = p2s[j];
            const float* wp = &Wt[(size_t)(t * 64 + j) * 16];
#pragma unroll
            for (int k = 0; k < 16; k++) s[k] += wp[k] * pj;
        }
        float p1v = p1s[t];
#pragma unroll
        for (int k = 0; k < 16; k++) scp[t * 16 + k] = p1v * s[k];
    }
    __syncthreads();
    if (t < 16) {
        float acc = tb[t];
        for (int i = 0; i < 64; i++) acc += scp[i * 16 + t];
        float blk = 0.0f;
        for (int i = 0; i < 64; i++) blk += Wtb[t * 128 + i] * p1s[i];
        for (int i = 0; i < 64; i++) blk += Wtb[t * 128 + 64 + i] * p2s[i];
        float tv = acc + blk;
        feat[t] = fmaxf(tv, 0.0f);
        int C_lo = (t == 0) ? NPG * NPG : cdf_s[t - 1];
        int C_hi = (t == 15) ? 0 : cdf_s[t];
        feat[16 + t] = (float)(C_lo - C_hi) * (1.0f / ((float)NPG * (float)NPG));
    }
    __syncthreads();
    if (t < 32) {
        float acc = b1[t];
        for (int i = 0; i < 32; i++) acc += feat[i] * W1[i * 32 + t];
        hs[t] = fmaxf(acc, 0.0f);
    }
    __syncthreads();
    if (t == 0) {
        float acc = bs[0];
        for (int j = 0; j < 32; j++) acc += hs[j] * Ws[j];
        out[b] = sigmoidf_(acc);
    }
}

// ---------------- launcher ----------------
extern "C" void kernel_launch(void* const* d_in, const int* in_sizes, int n_in,
                              void* d_out, int out_size) {
    const float* x1  = (const float*)d_in[0];
    const float* x2  = (const float*)d_in[1];
    const int* ei1   = (const int*)d_in[2];
    const int* ei2   = (const int*)d_in[3];
    const float* Wc1 = (const float*)d_in[6];
    const float* bc1 = (const float*)d_in[7];
    const float* Wc2 = (const float*)d_in[8];
    const float* bc2 = (const float*)d_in[9];
    const float* Wc3 = (const float*)d_in[10];
    const float* bc3 = (const float*)d_in[11];
    const float* Watt = (const float*)d_in[12];
    const float* Wt  = (const float*)d_in[13];
    const float* Wtb = (const float*)d_in[14];
    const float* tb  = (const float*)d_in[15];
    const float* W1  = (const float*)d_in[16];
    const float* b1  = (const float*)d_in[17];
    const float* Ws  = (const float*)d_in[18];
    const float* bs  = (const float*)d_in[19];
    float* out = (float*)d_out;

    void* p;
    float *a0, *a1, *b0, *b1p, *f0, *f1;
    cudaGetSymbolAddress(&p, g_bufA);
    a0 = (float*)p; a1 = a0 + (size_t)NTOT * D_F1;
    cudaGetSymbolAddress(&p, g_bufB);
    b0 = (float*)p; b1p = b0 + (size_t)NTOT * D_F1;
    cudaGetSymbolAddress(&p, g_feat);
    f0 = (float*)p; f1 = f0 + (size_t)NTOT * D_F3;

    // opt-in to 128 KB dynamic smem for the fused agg+pool kernel (idempotent)
    cudaFuncSetAttribute(agg_pool_k, cudaFuncAttributeMaxDynamicSharedMemorySize,
                         NPG * D_F3 * 4);

    init_k<<<NTOT / 256, 256>>>();

    // CSR build for BOTH sides (batched over grid.y)
    deg_k<<<dim3(NEDGE / 256, 2), 256>>>(ei1 + NEDGE, ei2 + NEDGE);
    scanA_k<<<dim3(256, 2), 256>>>();
    scanC_k<<<dim3(256, 2), 256>>>();
    scatter_k<<<dim3(NEDGE / 256, 2), 256>>>(ei1, ei2);

    // conv pipeline
    agg_k<32, 8, false, false><<<dim3(NB, 2, 1), 1024>>>(x1, x2, nullptr, a0, a1);
    gemm_mma_k<32, 128, true, true><<<dim3(NTOT / 128, 2), 256>>>(a0, a1, Wc1, bc1, b0, b1p);

    gemm_mma_k<128, 96, false, false><<<dim3(NTOT / 128, 2), 256>>>(b0, b1p, Wc2, nullptr, a0, a1);
    // layer-2 agg channel-split: each block handles 12 of 24 chunks (98KB L1 slab)
    agg_k<96, 12, true, true><<<dim3(NB, 2, 2), 1024>>>(a0, a1, bc2, b0, b1p);

    gemm_mma_k<96, 64, false, false><<<dim3(NTOT / 128, 2), 256>>>(b0, b1p, Wc3, nullptr, a0, a1);
    agg_pool_k<<<dim3(NB, 2), 1024, NPG * D_F3 * 4>>>(a0, a1, bc3, f0, f1, Watt);

    sim_mma_k<<<dim3(4, 4, NB), 256>>>();
    hist_final_k<<<NB, 1024>>>(Wt, Wtb, tb, W1, b1, Ws, bs, out);
}

// round 16
// speedup vs baseline: 1.1782x; 1.0291x over previous
#include <cuda_runtime.h>
#include <cuda_fp16.h>
#include <math.h>
#include <cfloat>
#include <stdint.h>

// ---------------- problem dims (fixed) ----------------
#define NTOT  65536      // nodes per side (B*N)
#define NEDGE 524288     // edges per side
#define NB    128        // graphs
#define NPG   512        // nodes per graph
#define D_F1  128
#define D_F2  96
#define D_F3  64
#define D_BINS 16

// ---------------- device scratch (per-side slabs for batched launches) -----
__device__ float g_bufA[2][NTOT * D_F1];
__device__ float g_bufB[2][NTOT * D_F1];
__device__ float g_feat[2][NTOT * D_F3];
__device__ float g_dinv[2][NTOT];
__device__ int   g_degi[2][NTOT];
__device__ int   g_row[2][NTOT + 1];
__device__ int   g_cursor[2][NTOT];
__device__ int   g_bsum[2][256];
__device__ int2  g_epack[2][NEDGE];                  // {src, norm bits}
__device__ __half g_simh[(size_t)NB * NPG * NPG];   // fp16 similarity scores
__device__ float g_smin[NB];
__device__ float g_smax[NB];
__device__ float g_pool[2][NB * D_F3];

__device__ __forceinline__ float sigmoidf_(float x) { return 1.0f / (1.0f + expf(-x)); }

__device__ __forceinline__ void atomicMinFloat(float* addr, float val) {
    int old = __float_as_int(*addr);
    while (__int_as_float(old) > val) {
        int assumed = old;
        old = atomicCAS((int*)addr, assumed, __float_as_int(val));
        if (old == assumed) break;
    }
}
__device__ __forceinline__ void atomicMaxFloat(float* addr, float val) {
    int old = __float_as_int(*addr);
    while (__int_as_float(old) < val) {
        int assumed = old;
        old = atomicCAS((int*)addr, assumed, __float_as_int(val));
        if (old == assumed) break;
    }
}

// ---------------- bf16x3 helpers (fp32 emulation via bf16 split) -----------
__device__ __forceinline__ void split2(float x0, float x1, uint32_t& h, uint32_t& l) {
    asm("cvt.rn.bf16x2.f32 %0, %1, %2;" : "=r"(h) : "f"(x1), "f"(x0));
    float r0 = x0 - __uint_as_float(h << 16);
    float r1 = x1 - __uint_as_float(h & 0xffff0000u);
    asm("cvt.rn.bf16x2.f32 %0, %1, %2;" : "=r"(l) : "f"(r1), "f"(r0));
}
__device__ __forceinline__ void mma_bf16(float* d, const uint32_t* a, const uint32_t* b) {
    asm volatile(
        "mma.sync.aligned.m16n8k16.row.col.f32.bf16.bf16.f32 "
        "{%0,%1,%2,%3}, {%4,%5,%6,%7}, {%8,%9}, {%0,%1,%2,%3};\n"
        : "+f"(d[0]), "+f"(d[1]), "+f"(d[2]), "+f"(d[3])
        : "r"(a[0]), "r"(a[1]), "r"(a[2]), "r"(a[3]), "r"(b[0]), "r"(b[1]));
}

// block-wide exclusive scan of 256 ints (one value per thread)
__device__ __forceinline__ int block_exscan_256(int v, int* sm8) {
    int lane = threadIdx.x & 31, w = threadIdx.x >> 5;
    int x = v;
#pragma unroll
    for (int o = 1; o < 32; o <<= 1) {
        int y = __shfl_up_sync(0xffffffffu, x, o);
        if (lane >= o) x += y;
    }
    if (lane == 31) sm8[w] = x;
    __syncthreads();
    if (threadIdx.x < 8) {
        int s = sm8[threadIdx.x];
#pragma unroll
        for (int o = 1; o < 8; o <<= 1) {
            int y = __shfl_up_sync(0xffu, s, o);
            if ((int)threadIdx.x >= o) s += y;
        }
        sm8[threadIdx.x] = s;
    }
    __syncthreads();
    int woff = w ? sm8[w - 1] : 0;
    return woff + x - v;
}

// ---------------- init ----------------
__global__ void init_k() {
    int i = blockIdx.x * blockDim.x + threadIdx.x;
    if (i < NTOT) { g_degi[0][i] = 0; g_degi[1][i] = 0; }
    if (i < NB) { g_smin[i] = FLT_MAX; g_smax[i] = -FLT_MAX; }
}

// ---------------- degree (both sides via grid.y) ----------------
__global__ void deg_k(const int* __restrict__ dst0, const int* __restrict__ dst1) {
    int side = blockIdx.y;
    const int* dst = side ? dst1 : dst0;
    int e = blockIdx.x * blockDim.x + threadIdx.x;
    if (e < NEDGE) atomicAdd(&g_degi[side][dst[e]], 1);
}

// ---------------- 2-phase parallel scan (A computes dinv + block sums) -----
__global__ void scanA_k() {
    int side = blockIdx.y;
    int i = blockIdx.x * 256 + threadIdx.x;
    int v = g_degi[side][i];
    g_dinv[side][i] = rsqrtf((float)v + 1.0f);
#pragma unroll
    for (int o = 16; o; o >>= 1) v += __shfl_xor_sync(0xffffffffu, v, o);
    __shared__ int sm[8];
    if ((threadIdx.x & 31) == 0) sm[threadIdx.x >> 5] = v;
    __syncthreads();
    if (threadIdx.x == 0) {
        int s = 0;
#pragma unroll
        for (int j = 0; j < 8; j++) s += sm[j];
        g_bsum[side][blockIdx.x] = s;
    }
}
__global__ void scanC_k() {
    int side = blockIdx.y;
    int bid = blockIdx.x;
    int t = threadIdx.x;
    int lane = t & 31, w = t >> 5;
    int pv = (t < bid) ? g_bsum[side][t] : 0;
#pragma unroll
    for (int o = 16; o; o >>= 1) pv += __shfl_xor_sync(0xffffffffu, pv, o);
    __shared__ int rsm[8];
    if (lane == 0) rsm[w] = pv;
    __syncthreads();
    __shared__ int prefix_s;
    if (t == 0) {
        int s = 0;
#pragma unroll
        for (int j = 0; j < 8; j++) s += rsm[j];
        prefix_s = s;
    }
    __syncthreads();
    int prefix = prefix_s;
    int i = bid * 256 + t;
    int d = g_degi[side][i];
    __shared__ int sm[8];
    int ex = block_exscan_256(d, sm);
    int off = prefix + ex;
    g_row[side][i] = off;
    g_cursor[side][i] = off;
    if (i == NTOT - 1) g_row[side][NTOT] = NEDGE;
}

// ---------------- scatter edges into CSR order (packed src+norm) -----------
__global__ void scatter_k(const int* __restrict__ ei0, const int* __restrict__ ei1) {
    int side = blockIdx.y;
    const int* ei = side ? ei1 : ei0;
    const int* src = ei;
    const int* dst = ei + NEDGE;
    int e = blockIdx.x * blockDim.x + threadIdx.x;
    if (e >= NEDGE) return;
    int s = src[e], d = dst[e];
    int pos = atomicAdd(&g_cursor[side][d], 1);
    float nm = g_dinv[side][s] * g_dinv[side][d];
    g_epack[side][pos] = make_int2(s, __float_as_int(nm));
}

// ---------------- graph-per-block aggregation (L1-resident gathers) --------
template <int OUT, bool BIAS, bool RELU>
__global__ void agg_k(const float* __restrict__ xw0, const float* __restrict__ xw1,
                      const float* __restrict__ bias,
                      float* __restrict__ out0, float* __restrict__ out1) {
    constexpr int C4 = OUT / 4;
    int side = blockIdx.y;
    const float* xw = side ? xw1 : xw0;
    float* out = side ? out1 : out0;
    int base = blockIdx.x * NPG;
    const float4* xw4 = (const float4*)xw;
    float4* out4 = (float4*)out;
    for (int wi = threadIdx.x; wi < NPG * C4; wi += blockDim.x) {
        int node = base + wi / C4;
        int chunk = wi % C4;
        float dv = g_dinv[side][node];
        float dv2 = dv * dv;
        float4 v = xw4[(size_t)node * C4 + chunk];
        float4 acc = make_float4(v.x * dv2, v.y * dv2, v.z * dv2, v.w * dv2);
        int beg = g_row[side][node], end = g_row[side][node + 1];
        for (int e = beg; e < end; e++) {
            int2 ep = g_epack[side][e];
            float nm = __int_as_float(ep.y);
            float4 u = xw4[(size_t)ep.x * C4 + chunk];
            acc.x += u.x * nm; acc.y += u.y * nm; acc.z += u.z * nm; acc.w += u.w * nm;
        }
        if (BIAS) {
            acc.x += bias[chunk * 4 + 0];
            acc.y += bias[chunk * 4 + 1];
            acc.z += bias[chunk * 4 + 2];
            acc.w += bias[chunk * 4 + 3];
        }
        if (RELU) {
            acc.x = fmaxf(acc.x, 0.f); acc.y = fmaxf(acc.y, 0.f);
            acc.z = fmaxf(acc.z, 0.f); acc.w = fmaxf(acc.w, 0.f);
        }
        out4[(size_t)node * C4 + chunk] = acc;
    }
}

// ---------------- agg3 + attention pool fused (one block per graph) --------
__global__ void agg_pool_k(const float* __restrict__ xw0, const float* __restrict__ xw1,
                           const float* __restrict__ bias,
                           float* __restrict__ out0, float* __restrict__ out1,
                           const float* __restrict__ Watt) {
    constexpr int C4 = 16;
    extern __shared__ float sfeat[];       // NPG*64 floats = 128 KB
    int side = blockIdx.y;
    int b = blockIdx.x;
    const float* xw = side ? xw1 : xw0;
    float* out = side ? out1 : out0;
    int base = b * NPG;
    const float4* xw4 = (const float4*)xw;
    float4* out4 = (float4*)out;
    float4* sf4 = (float4*)sfeat;
    int t = threadIdx.x;                    // 1024

    // ---- aggregation ----
    for (int wi = t; wi < NPG * C4; wi += 1024) {
        int node = base + wi / C4;
        int chunk = wi % C4;
        float dv = g_dinv[side][node];
        float dv2 = dv * dv;
        float4 v = xw4[(size_t)node * C4 + chunk];
        float4 acc = make_float4(v.x * dv2, v.y * dv2, v.z * dv2, v.w * dv2);
        int beg = g_row[side][node], end = g_row[side][node + 1];
        for (int e = beg; e < end; e++) {
            int2 ep = g_epack[side][e];
            float nm = __int_as_float(ep.y);
            float4 u = xw4[(size_t)ep.x * C4 + chunk];
            acc.x += u.x * nm; acc.y += u.y * nm; acc.z += u.z * nm; acc.w += u.w * nm;
        }
        acc.x += bias[chunk * 4 + 0];
        acc.y += bias[chunk * 4 + 1];
        acc.z += bias[chunk * 4 + 2];
        acc.w += bias[chunk * 4 + 3];
        out4[(size_t)node * C4 + chunk] = acc;
        sf4[wi] = acc;
    }
    __syncthreads();

    // ---- attention pooling on the smem slab ----
    __shared__ float p16[16][64];
    __shared__ float meanc[64];
    __shared__ float ctx[64];
    __shared__ float wsum[32][64];
    int d = t & 63, g = t >> 6;
    float loc = 0.0f;
    for (int r = g; r < NPG; r += 16) loc += sfeat[r * 64 + d];
    p16[g][d] = loc;
    __syncthreads();
    if (t < 64) {
        float s = 0.0f;
#pragma unroll
        for (int j = 0; j < 16; j++) s += p16[j][t];
        meanc[t] = s * (1.0f / NPG);
    }
    __syncthreads();
    if (t < 64) {
        float c = 0.0f;
        for (int i = 0; i < 64; i++) c += meanc[i] * Watt[i * 64 + t];
        ctx[t] = tanhf(c);
    }
    __syncthreads();
    int w = t >> 5, l = t & 31;
    float a0 = 0.0f, a1 = 0.0f;
    float c0 = ctx[l], c1 = ctx[l + 32];
    for (int r = w * 16; r < w * 16 + 16; r++) {
        float v0 = sfeat[r * 64 + l], v1 = sfeat[r * 64 + 32 + l];
        float dp = v0 * c0 + v1 * c1;
#pragma unroll
        for (int o = 16; o; o >>= 1) dp += __shfl_xor_sync(0xffffffffu, dp, o);
        float coef = sigmoidf_(dp);
        a0 += v0 * coef;
        a1 += v1 * coef;
    }
    wsum[w][l] = a0;
    wsum[w][l + 32] = a1;
    __syncthreads();
    if (t < 64) {
        float s = 0.0f;
#pragma unroll
        for (int w2 = 0; w2 < 32; w2++) s += wsum[w2][t];
        g_pool[side][b * 64 + t] = s;
    }
}

// ---------------- bf16x3 tensor-core GEMM (both sides via grid.y) ----------
template <int KIN, int NOUT, bool BIAS, bool RELU>
__global__ void gemm_mma_k(const float* __restrict__ x0, const float* __restrict__ x1,
                           const float* __restrict__ W, const float* __restrict__ bias,
                           float* __restrict__ out0, float* __restrict__ out1) {
    constexpr int KC = 32;
    constexpr int KP = KC / 2;
    constexpr int NT = NOUT / 8;
    constexpr int XS = 20;
    constexpr int WS = 20;
    __shared__ uint32_t Xh[128 * XS];
    __shared__ uint32_t Xl[128 * XS];
    __shared__ uint32_t Wh[NOUT * WS];
    __shared__ uint32_t Wl[NOUT * WS];
    int side = blockIdx.y;
    const float* x = side ? x1 : x0;
    float* out = side ? out1 : out0;
    int tid = threadIdx.x;
    int warp = tid >> 5, lane = tid & 31;
    size_t m0 = (size_t)blockIdx.x * 128;
    float acc[NT][4];
#pragma unroll
    for (int i = 0; i < NT; i++)
#pragma unroll
        for (int j = 0; j < 4; j++) acc[i][j] = 0.0f;

    for (int k0 = 0; k0 < KIN; k0 += KC) {
        for (int i = tid; i < 128 * 8; i += 256) {
            int r = i >> 3, q = i & 7;
            float4 v = *(const float4*)&x[(m0 + r) * KIN + k0 + q * 4];
            uint32_t h0, l0, h1, l1;
            split2(v.x, v.y, h0, l0);
            split2(v.z, v.w, h1, l1);
            Xh[r * XS + q * 2] = h0;     Xh[r * XS + q * 2 + 1] = h1;
            Xl[r * XS + q * 2] = l0;     Xl[r * XS + q * 2 + 1] = l1;
        }
        for (int i = tid; i < NOUT * KP; i += 256) {
            int kp = i / NOUT, n = i % NOUT;
            float w0 = W[(size_t)(k0 + 2 * kp) * NOUT + n];
            float w1 = W[(size_t)(k0 + 2 * kp + 1) * NOUT + n];
            uint32_t h, l;
            split2(w0, w1, h, l);
            Wh[n * WS + kp] = h;
            Wl[n * WS + kp] = l;
        }
        __syncthreads();
#pragma unroll
        for (int s = 0; s < 2; s++) {
            int kb = s * 8 + (lane & 3);
            uint32_t ah[4], al[4];
            int arow = warp * 16 + (lane >> 2);
            ah[0] = Xh[arow * XS + kb];           al[0] = Xl[arow * XS + kb];
            ah[1] = Xh[(arow + 8) * XS + kb];     al[1] = Xl[(arow + 8) * XS + kb];
            ah[2] = Xh[arow * XS + kb + 4];       al[2] = Xl[arow * XS + kb + 4];
            ah[3] = Xh[(arow + 8) * XS + kb + 4]; al[3] = Xl[(arow + 8) * XS + kb + 4];
            int bn = lane >> 2;
#pragma unroll
            for (int nt = 0; nt < NT; nt++) {
                uint32_t bh[2], bl[2];
                int nb = (nt * 8 + bn) * WS;
                bh[0] = Wh[nb + kb]; bh[1] = Wh[nb + kb + 4];
                bl[0] = Wl[nb + kb]; bl[1] = Wl[nb + kb + 4];
                mma_bf16(acc[nt], ah, bh);
                mma_bf16(acc[nt], ah, bl);
                mma_bf16(acc[nt], al, bh);
            }
        }
        __syncthreads();
    }
    size_t row = m0 + warp * 16 + (lane >> 2);
    int col0 = (lane & 3) * 2;
#pragma unroll
    for (int nt = 0; nt < NT; nt++) {
        int c = nt * 8 + col0;
        float b0 = BIAS ? bias[c] : 0.0f, b1 = BIAS ? bias[c + 1] : 0.0f;
        float v0 = acc[nt][0] + b0, v1 = acc[nt][1] + b1;
        float v2 = acc[nt][2] + b0, v3 = acc[nt][3] + b1;
        if (RELU) {
            v0 = fmaxf(v0, 0.f); v1 = fmaxf(v1, 0.f);
            v2 = fmaxf(v2, 0.f); v3 = fmaxf(v3, 0.f);
        }
        *(float2*)&out[row * NOUT + c] = make_float2(v0, v1);
        *(float2*)&out[(row + 8) * NOUT + c] = make_float2(v2, v3);
    }
}

// ---------------- similarity via bf16x3 mma, 128x128 tile, fp16 store ------
__global__ void sim_mma_k() {
    constexpr int XS = 20;
    int b = blockIdx.z;
    int i0 = blockIdx.y * 128, j0 = blockIdx.x * 128;
    __shared__ uint32_t Ah_s[128 * XS];
    __shared__ uint32_t Al_s[128 * XS];
    __shared__ uint32_t Bh_s[128 * XS];
    __shared__ uint32_t Bl_s[128 * XS];
    const float* f1 = &g_feat[0][(size_t)(b * NPG + i0) * 64];
    const float* f2 = &g_feat[1][(size_t)(b * NPG + j0) * 64];
    int tid = threadIdx.x;
    int warp = tid >> 5, lane = tid & 31;
    int wm = warp >> 2, wn = warp & 3;
    float acc[4][4][4];
#pragma unroll
    for (int mt = 0; mt < 4; mt++)
#pragma unroll
        for (int nt = 0; nt < 4; nt++)
#pragma unroll
            for (int j = 0; j < 4; j++) acc[mt][nt][j] = 0.0f;

    for (int k0 = 0; k0 < 64; k0 += 32) {
        for (int i = tid; i < 128 * 8; i += 256) {
            int r = i >> 3, q = i & 7;
            float4 va = *(const float4*)&f1[r * 64 + k0 + q * 4];
            float4 vb = *(const float4*)&f2[r * 64 + k0 + q * 4];
            uint32_t h0, l0, h1, l1;
            split2(va.x, va.y, h0, l0);
            split2(va.z, va.w, h1, l1);
            Ah_s[r * XS + q * 2] = h0;     Ah_s[r * XS + q * 2 + 1] = h1;
            Al_s[r * XS + q * 2] = l0;     Al_s[r * XS + q * 2 + 1] = l1;
            split2(vb.x, vb.y, h0, l0);
            split2(vb.z, vb.w, h1, l1);
            Bh_s[r * XS + q * 2] = h0;     Bh_s[r * XS + q * 2 + 1] = h1;
            Bl_s[r * XS + q * 2] = l0;     Bl_s[r * XS + q * 2 + 1] = l1;
        }
        __syncthreads();
#pragma unroll
        for (int s = 0; s < 2; s++) {
            int kb = s * 8 + (lane & 3);
            uint32_t ah[4][4], al[4][4], bh[4][2], bl[4][2];
#pragma unroll
            for (int mt = 0; mt < 4; mt++) {
                int arow = wm * 64 + mt * 16 + (lane >> 2);
                ah[mt][0] = Ah_s[arow * XS + kb];
                ah[mt][1] = Ah_s[(arow + 8) * XS + kb];
                ah[mt][2] = Ah_s[arow * XS + kb + 4];
                ah[mt][3] = Ah_s[(arow + 8) * XS + kb + 4];
                al[mt][0] = Al_s[arow * XS + kb];
                al[mt][1] = Al_s[(arow + 8) * XS + kb];
                al[mt][2] = Al_s[arow * XS + kb + 4];
                al[mt][3] = Al_s[(arow + 8) * XS + kb + 4];
            }
#pragma unroll
            for (int nt = 0; nt < 4; nt++) {
                int bnode = wn * 32 + nt * 8 + (lane >> 2);
                bh[nt][0] = Bh_s[bnode * XS + kb];
                bh[nt][1] = Bh_s[bnode * XS + kb + 4];
                bl[nt][0] = Bl_s[bnode * XS + kb];
                bl[nt][1] = Bl_s[bnode * XS + kb + 4];
            }
#pragma unroll
            for (int mt = 0; mt < 4; mt++)
#pragma unroll
                for (int nt = 0; nt < 4; nt++) {
                    mma_bf16(acc[mt][nt], ah[mt], bh[nt]);
                    mma_bf16(acc[mt][nt], ah[mt], bl[nt]);
                    mma_bf16(acc[mt][nt], al[mt], bh[nt]);
                }
        }
        __syncthreads();
    }
    float lmin = FLT_MAX, lmax = -FLT_MAX;
    __half* sp = &g_simh[(size_t)b * NPG * NPG];
    int col0 = (lane & 3) * 2;
#pragma unroll
    for (int mt = 0; mt < 4; mt++) {
        size_t r0 = (size_t)(i0 + wm * 64 + mt * 16 + (lane >> 2));
#pragma unroll
        for (int nt = 0; nt < 4; nt++) {
            int c = j0 + wn * 32 + nt * 8 + col0;
            float v0 = acc[mt][nt][0], v1 = acc[mt][nt][1];
            float v2 = acc[mt][nt][2], v3 = acc[mt][nt][3];
            lmin = fminf(lmin, fminf(fminf(v0, v1), fminf(v2, v3)));
            lmax = fmaxf(lmax, fmaxf(fmaxf(v0, v1), fmaxf(v2, v3)));
            *(__half2*)&sp[r0 * NPG + c] = __floats2half2_rn(v0, v1);
            *(__half2*)&sp[(r0 + 8) * NPG + c] = __floats2half2_rn(v2, v3);
        }
    }
    __shared__ float rmin[256], rmax[256];
    rmin[tid] = lmin;
    rmax[tid] = lmax;
    __syncthreads();
    for (int s = 128; s > 0; s >>= 1) {
        if (tid < s) {
            rmin[tid] = fminf(rmin[tid], rmin[tid + s]);
            rmax[tid] = fmaxf(rmax[tid], rmax[tid + s]);
        }
        __syncthreads();
    }
    if (tid == 0) {
        atomicMinFloat(&g_smin[b], rmin[0]);
        atomicMaxFloat(&g_smax[b], rmax[0]);
    }
}

// ---------------- histogram (threshold CDF, half2, 2-way ILP) + head -------
__global__ void hist_final_k(const float* __restrict__ Wt, const float* __restrict__ Wtb,
                             const float* __restrict__ tb, const float* __restrict__ W1,
                             const float* __restrict__ b1, const float* __restrict__ Ws,
                             const float* __restrict__ bs, float* __restrict__ out) {
    int b = blockIdx.x;
    int t = threadIdx.x;
    int lane = t & 31, warp = t >> 5;     // 32 warps
    __shared__ __half2 thr_s[15];
    if (t < 15) {
        float vmin = sigmoidf_(g_smin[b]);
        float vmax = sigmoidf_(g_smax[b]);
        float width = (vmax - vmin) * (1.0f / D_BINS);
        float thr;
        if (width > 0.0f) {
            float bnd = vmin + (float)(t + 1) * width;
            thr = logf(bnd / (1.0f - bnd));
        } else {
            thr = FLT_MAX;
        }
        thr_s[t] = __float2half2_rn(thr);
    }
    __syncthreads();
    __half2 T2[15];
#pragma unroll
    for (int k = 0; k < 15; k++) T2[k] = thr_s[k];

    const uint4* qp = (const uint4*)&g_simh[(size_t)b * NPG * NPG];
    __half2 C2[15];
#pragma unroll
    for (int k = 0; k < 15; k++) C2[k] = __float2half2_rn(0.0f);
    // two independent streams of 16384 uint4 each; per-half count <= 128 (exact fp16)
    for (int i = t; i < 16384; i += 1024) {
        uint4 qa = qp[i];
        uint4 qb = qp[i + 16384];
        __half2 a0 = *(__half2*)&qa.x, a1 = *(__half2*)&qa.y;
        __half2 a2 = *(__half2*)&qa.z, a3 = *(__half2*)&qa.w;
        __half2 b0 = *(__half2*)&qb.x, b1h = *(__half2*)&qb.y;
        __half2 b2 = *(__half2*)&qb.z, b3 = *(__half2*)&qb.w;
#pragma unroll
        for (int k = 0; k < 15; k++) {
            C2[k] = __hadd2(C2[k], __hge2(a0, T2[k]));
            C2[k] = __hadd2(C2[k], __hge2(a1, T2[k]));
            C2[k] = __hadd2(C2[k], __hge2(a2, T2[k]));
            C2[k] = __hadd2(C2[k], __hge2(a3, T2[k]));
            C2[k] = __hadd2(C2[k], __hge2(b0, T2[k]));
            C2[k] = __hadd2(C2[k], __hge2(b1h, T2[k]));
            C2[k] = __hadd2(C2[k], __hge2(b2, T2[k]));
            C2[k] = __hadd2(C2[k], __hge2(b3, T2[k]));
        }
    }
    __shared__ int red[32][16];
#pragma unroll
    for (int k = 0; k < 15; k++) {
        int c = (int)(__low2float(C2[k]) + __high2float(C2[k]));
#pragma unroll
        for (int o = 16; o; o >>= 1) c += __shfl_xor_sync(0xffffffffu, c, o);
        if (lane == 0) red[warp][k] = c;
    }
    __syncthreads();
    __shared__ int cdf_s[15];
    if (t < 15) {
        int s = 0;
#pragma unroll
        for (int w = 0; w < 32; w++) s += red[w][t];
        cdf_s[t] = s;
    }

    // ---- final head ----
    __shared__ float p1s[64], p2s[64];
    __shared__ float scp[64 * 16];
    __shared__ float feat[32];
    __shared__ float hs[32];
    if (t < 64) {
        p1s[t] = g_pool[0][b * 64 + t];
        p2s[t] = g_pool[1][b * 64 + t];
    }
    __syncthreads();
    if (t < 64) {
        float s[16];
#pragma unroll
        for (int k = 0; k < 16; k++) s[k] = 0.0f;
        for (int j = 0; j < 64; j++) {
            float pj = p2s[j];
            const float* wp = &Wt[(size_t)(t * 64 + j) * 16];
#pragma unroll
            for (int k = 0; k < 16; k++) s[k] += wp[k] * pj;
        }
        float p1v = p1s[t];
#pragma unroll
        for (int k = 0; k < 16; k++) scp[t * 16 + k] = p1v * s[k];
    }
    __syncthreads();
    if (t < 16) {
        float acc = tb[t];
        for (int i = 0; i < 64; i++) acc += scp[i * 16 + t];
        float blk = 0.0f;
        for (int i = 0; i < 64; i++) blk += Wtb[t * 128 + i] * p1s[i];
        for (int i = 0; i < 64; i++) blk += Wtb[t * 128 + 64 + i] * p2s[i];
        float tv = acc + blk;
        feat[t] = fmaxf(tv, 0.0f);
        int C_lo = (t == 0) ? NPG * NPG : cdf_s[t - 1];
        int C_hi = (t == 15) ? 0 : cdf_s[t];
        feat[16 + t] = (float)(C_lo - C_hi) * (1.0f / ((float)NPG * (float)NPG));
    }
    __syncthreads();
    if (t < 32) {
        float acc = b1[t];
        for (int i = 0; i < 32; i++) acc += feat[i] * W1[i * 32 + t];
        hs[t] = fmaxf(acc, 0.0f);
    }
    __syncthreads();
    if (t == 0) {
        float acc = bs[0];
        for (int j = 0; j < 32; j++) acc += hs[j] * Ws[j];
        out[b] = sigmoidf_(acc);
    }
}

// ---------------- launcher ----------------
extern "C" void kernel_launch(void* const* d_in, const int* in_sizes, int n_in,
                              void* d_out, int out_size) {
    const float* x1  = (const float*)d_in[0];
    const float* x2  = (const float*)d_in[1];
    const int* ei1   = (const int*)d_in[2];
    const int* ei2   = (const int*)d_in[3];
    const float* Wc1 = (const float*)d_in[6];
    const float* bc1 = (const float*)d_in[7];
    const float* Wc2 = (const float*)d_in[8];
    const float* bc2 = (const float*)d_in[9];
    const float* Wc3 = (const float*)d_in[10];
    const float* bc3 = (const float*)d_in[11];
    const float* Watt = (const float*)d_in[12];
    const float* Wt  = (const float*)d_in[13];
    const float* Wtb = (const float*)d_in[14];
    const float* tb  = (const float*)d_in[15];
    const float* W1  = (const float*)d_in[16];
    const float* b1  = (const float*)d_in[17];
    const float* Ws  = (const float*)d_in[18];
    const float* bs  = (const float*)d_in[19];
    float* out = (float*)d_out;

    void* p;
    float *a0, *a1, *b0, *b1p, *f0, *f1;
    cudaGetSymbolAddress(&p, g_bufA);
    a0 = (float*)p; a1 = a0 + (size_t)NTOT * D_F1;
    cudaGetSymbolAddress(&p, g_bufB);
    b0 = (float*)p; b1p = b0 + (size_t)NTOT * D_F1;
    cudaGetSymbolAddress(&p, g_feat);
    f0 = (float*)p; f1 = f0 + (size_t)NTOT * D_F3;

    // opt-in to 128 KB dynamic smem for the fused agg+pool kernel (idempotent)
    cudaFuncSetAttribute(agg_pool_k, cudaFuncAttributeMaxDynamicSharedMemorySize,
                         NPG * D_F3 * 4);

    init_k<<<NTOT / 256, 256>>>();

    // CSR build for BOTH sides (batched over grid.y)
    deg_k<<<dim3(NEDGE / 256, 2), 256>>>(ei1 + NEDGE, ei2 + NEDGE);
    scanA_k<<<dim3(256, 2), 256>>>();
    scanC_k<<<dim3(256, 2), 256>>>();
    scatter_k<<<dim3(NEDGE / 256, 2), 256>>>(ei1, ei2);

    // conv pipeline (R13 configuration: full-width agg blocks, one per graph)
    agg_k<32, false, false><<<dim3(NB, 2), 1024>>>(x1, x2, nullptr, a0, a1);
    gemm_mma_k<32, 128, true, true><<<dim3(NTOT / 128, 2), 256>>>(a0, a1, Wc1, bc1, b0, b1p);

    gemm_mma_k<128, 96, false, false><<<dim3(NTOT / 128, 2), 256>>>(b0, b1p, Wc2, nullptr, a0, a1);
    agg_k<96, true, true><<<dim3(NB, 2), 1024>>>(a0, a1, bc2, b0, b1p);

    gemm_mma_k<96, 64, false, false><<<dim3(NTOT / 128, 2), 256>>>(b0, b1p, Wc3, nullptr, a0, a1);
    agg_pool_k<<<dim3(NB, 2), 1024, NPG * D_F3 * 4>>>(a0, a1, bc3, f0, f1, Watt);

    sim_mma_k<<<dim3(4, 4, NB), 256>>>();
    hist_final_k<<<NB, 1024>>>(Wt, Wtb, tb, W1, b1, Ws, bs, out);
}

// round 17
// speedup vs baseline: 1.1959x; 1.0150x over previous
#include <cuda_runtime.h>
#include <cuda_fp16.h>
#include <math.h>
#include <cfloat>
#include <stdint.h>

// ---------------- problem dims (fixed) ----------------
#define NTOT  65536      // nodes per side (B*N)
#define NEDGE 524288     // edges per side
#define NB    128        // graphs
#define NPG   512        // nodes per graph
#define D_F1  128
#define D_F2  96
#define D_F3  64
#define D_BINS 16

// ---------------- device scratch (per-side slabs for batched launches) -----
// NOTE: g_degi is self-resetting (zeroed by scanC after use each call) and
// zero-initialized at module load, so no init kernel is needed.
__device__ float g_bufA[2][NTOT * D_F1];
__device__ float g_bufB[2][NTOT * D_F1];
__device__ float g_feat[2][NTOT * D_F3];
__device__ float g_dinv[2][NTOT];
__device__ int   g_degi[2][NTOT];
__device__ int   g_row[2][NTOT + 1];
__device__ int   g_cursor[2][NTOT];
__device__ int   g_bsum[2][256];
__device__ int2  g_epack[2][NEDGE];                  // {src, norm bits}
__device__ __half g_simh[(size_t)NB * NPG * NPG];   // fp16 similarity scores
__device__ float g_smin[NB];
__device__ float g_smax[NB];
__device__ float g_pool[2][NB * D_F3];

__device__ __forceinline__ float sigmoidf_(float x) { return 1.0f / (1.0f + expf(-x)); }

__device__ __forceinline__ void atomicMinFloat(float* addr, float val) {
    int old = __float_as_int(*addr);
    while (__int_as_float(old) > val) {
        int assumed = old;
        old = atomicCAS((int*)addr, assumed, __float_as_int(val));
        if (old == assumed) break;
    }
}
__device__ __forceinline__ void atomicMaxFloat(float* addr, float val) {
    int old = __float_as_int(*addr);
    while (__int_as_float(old) < val) {
        int assumed = old;
        old = atomicCAS((int*)addr, assumed, __float_as_int(val));
        if (old == assumed) break;
    }
}

// ---------------- bf16 helpers (fp32 emulation via bf16 split) -------------
__device__ __forceinline__ void split2(float x0, float x1, uint32_t& h, uint32_t& l) {
    asm("cvt.rn.bf16x2.f32 %0, %1, %2;" : "=r"(h) : "f"(x1), "f"(x0));
    float r0 = x0 - __uint_as_float(h << 16);
    float r1 = x1 - __uint_as_float(h & 0xffff0000u);
    asm("cvt.rn.bf16x2.f32 %0, %1, %2;" : "=r"(l) : "f"(r1), "f"(r0));
}
__device__ __forceinline__ uint32_t pack2(float x0, float x1) {
    uint32_t h;
    asm("cvt.rn.bf16x2.f32 %0, %1, %2;" : "=r"(h) : "f"(x1), "f"(x0));
    return h;
}
__device__ __forceinline__ void mma_bf16(float* d, const uint32_t* a, const uint32_t* b) {
    asm volatile(
        "mma.sync.aligned.m16n8k16.row.col.f32.bf16.bf16.f32 "
        "{%0,%1,%2,%3}, {%4,%5,%6,%7}, {%8,%9}, {%0,%1,%2,%3};\n"
        : "+f"(d[0]), "+f"(d[1]), "+f"(d[2]), "+f"(d[3])
        : "r"(a[0]), "r"(a[1]), "r"(a[2]), "r"(a[3]), "r"(b[0]), "r"(b[1]));
}

// block-wide exclusive scan of 256 ints (one value per thread)
__device__ __forceinline__ int block_exscan_256(int v, int* sm8) {
    int lane = threadIdx.x & 31, w = threadIdx.x >> 5;
    int x = v;
#pragma unroll
    for (int o = 1; o < 32; o <<= 1) {
        int y = __shfl_up_sync(0xffffffffu, x, o);
        if (lane >= o) x += y;
    }
    if (lane == 31) sm8[w] = x;
    __syncthreads();
    if (threadIdx.x < 8) {
        int s = sm8[threadIdx.x];
#pragma unroll
        for (int o = 1; o < 8; o <<= 1) {
            int y = __shfl_up_sync(0xffu, s, o);
            if ((int)threadIdx.x >= o) s += y;
        }
        sm8[threadIdx.x] = s;
    }
    __syncthreads();
    int woff = w ? sm8[w - 1] : 0;
    return woff + x - v;
}

// ---------------- degree (both sides via grid.y); also re-inits smin/smax --
__global__ void deg_k(const int* __restrict__ dst0, const int* __restrict__ dst1) {
    int side = blockIdx.y;
    if (blockIdx.x == 0 && side == 0 && threadIdx.x < NB) {
        g_smin[threadIdx.x] = FLT_MAX;
        g_smax[threadIdx.x] = -FLT_MAX;
    }
    const int* dst = side ? dst1 : dst0;
    int e = blockIdx.x * blockDim.x + threadIdx.x;
    if (e < NEDGE) atomicAdd(&g_degi[side][dst[e]], 1);
}

// ---------------- 2-phase parallel scan (A computes dinv + block sums) -----
__global__ void scanA_k() {
    int side = blockIdx.y;
    int i = blockIdx.x * 256 + threadIdx.x;
    int v = g_degi[side][i];
    g_dinv[side][i] = rsqrtf((float)v + 1.0f);
#pragma unroll
    for (int o = 16; o; o >>= 1) v += __shfl_xor_sync(0xffffffffu, v, o);
    __shared__ int sm[8];
    if ((threadIdx.x & 31) == 0) sm[threadIdx.x >> 5] = v;
    __syncthreads();
    if (threadIdx.x == 0) {
        int s = 0;
#pragma unroll
        for (int j = 0; j < 8; j++) s += sm[j];
        g_bsum[side][blockIdx.x] = s;
    }
}
// scanC: per-block exclusive scan; prefix via bsum reduce; resets degi to 0
__global__ void scanC_k() {
    int side = blockIdx.y;
    int bid = blockIdx.x;
    int t = threadIdx.x;
    int lane = t & 31, w = t >> 5;
    int pv = (t < bid) ? g_bsum[side][t] : 0;
#pragma unroll
    for (int o = 16; o; o >>= 1) pv += __shfl_xor_sync(0xffffffffu, pv, o);
    __shared__ int rsm[8];
    if (lane == 0) rsm[w] = pv;
    __syncthreads();
    __shared__ int prefix_s;
    if (t == 0) {
        int s = 0;
#pragma unroll
        for (int j = 0; j < 8; j++) s += rsm[j];
        prefix_s = s;
    }
    __syncthreads();
    int prefix = prefix_s;
    int i = bid * 256 + t;
    int d = g_degi[side][i];
    g_degi[side][i] = 0;              // self-reset for next graph replay
    __shared__ int sm[8];
    int ex = block_exscan_256(d, sm);
    int off = prefix + ex;
    g_row[side][i] = off;
    g_cursor[side][i] = off;
    if (i == NTOT - 1) g_row[side][NTOT] = NEDGE;
}

// ---------------- scatter edges into CSR order (packed src+norm) -----------
__global__ void scatter_k(const int* __restrict__ ei0, const int* __restrict__ ei1) {
    int side = blockIdx.y;
    const int* ei = side ? ei1 : ei0;
    const int* src = ei;
    const int* dst = ei + NEDGE;
    int e = blockIdx.x * blockDim.x + threadIdx.x;
    if (e >= NEDGE) return;
    int s = src[e], d = dst[e];
    int pos = atomicAdd(&g_cursor[side][d], 1);
    float nm = g_dinv[side][s] * g_dinv[side][d];
    g_epack[side][pos] = make_int2(s, __float_as_int(nm));
}

// ---------------- graph-per-block aggregation (L1-resident gathers) --------
template <int OUT, bool BIAS, bool RELU>
__global__ void agg_k(const float* __restrict__ xw0, const float* __restrict__ xw1,
                      const float* __restrict__ bias,
                      float* __restrict__ out0, float* __restrict__ out1) {
    constexpr int C4 = OUT / 4;
    int side = blockIdx.y;
    const float* xw = side ? xw1 : xw0;
    float* out = side ? out1 : out0;
    int base = blockIdx.x * NPG;
    const float4* xw4 = (const float4*)xw;
    float4* out4 = (float4*)out;
    for (int wi = threadIdx.x; wi < NPG * C4; wi += blockDim.x) {
        int node = base + wi / C4;
        int chunk = wi % C4;
        float dv = g_dinv[side][node];
        float dv2 = dv * dv;
        float4 v = xw4[(size_t)node * C4 + chunk];
        float4 acc = make_float4(v.x * dv2, v.y * dv2, v.z * dv2, v.w * dv2);
        int beg = g_row[side][node], end = g_row[side][node + 1];
        for (int e = beg; e < end; e++) {
            int2 ep = g_epack[side][e];
            float nm = __int_as_float(ep.y);
            float4 u = xw4[(size_t)ep.x * C4 + chunk];
            acc.x += u.x * nm; acc.y += u.y * nm; acc.z += u.z * nm; acc.w += u.w * nm;
        }
        if (BIAS) {
            acc.x += bias[chunk * 4 + 0];
            acc.y += bias[chunk * 4 + 1];
            acc.z += bias[chunk * 4 + 2];
            acc.w += bias[chunk * 4 + 3];
        }
        if (RELU) {
            acc.x = fmaxf(acc.x, 0.f); acc.y = fmaxf(acc.y, 0.f);
            acc.z = fmaxf(acc.z, 0.f); acc.w = fmaxf(acc.w, 0.f);
        }
        out4[(size_t)node * C4 + chunk] = acc;
    }
}

// ---------------- agg3 + attention pool fused (one block per graph) --------
__global__ void agg_pool_k(const float* __restrict__ xw0, const float* __restrict__ xw1,
                           const float* __restrict__ bias,
                           float* __restrict__ out0, float* __restrict__ out1,
                           const float* __restrict__ Watt) {
    constexpr int C4 = 16;
    extern __shared__ float sfeat[];       // NPG*64 floats = 128 KB
    int side = blockIdx.y;
    int b = blockIdx.x;
    const float* xw = side ? xw1 : xw0;
    float* out = side ? out1 : out0;
    int base = b * NPG;
    const float4* xw4 = (const float4*)xw;
    float4* out4 = (float4*)out;
    float4* sf4 = (float4*)sfeat;
    int t = threadIdx.x;                    // 1024

    // ---- aggregation ----
    for (int wi = t; wi < NPG * C4; wi += 1024) {
        int node = base + wi / C4;
        int chunk = wi % C4;
        float dv = g_dinv[side][node];
        float dv2 = dv * dv;
        float4 v = xw4[(size_t)node * C4 + chunk];
        float4 acc = make_float4(v.x * dv2, v.y * dv2, v.z * dv2, v.w * dv2);
        int beg = g_row[side][node], end = g_row[side][node + 1];
        for (int e = beg; e < end; e++) {
            int2 ep = g_epack[side][e];
            float nm = __int_as_float(ep.y);
            float4 u = xw4[(size_t)ep.x * C4 + chunk];
            acc.x += u.x * nm; acc.y += u.y * nm; acc.z += u.z * nm; acc.w += u.w * nm;
        }
        acc.x += bias[chunk * 4 + 0];
        acc.y += bias[chunk * 4 + 1];
        acc.z += bias[chunk * 4 + 2];
        acc.w += bias[chunk * 4 + 3];
        out4[(size_t)node * C4 + chunk] = acc;
        sf4[wi] = acc;
    }
    __syncthreads();

    // ---- attention pooling on the smem slab ----
    __shared__ float p16[16][64];
    __shared__ float meanc[64];
    __shared__ float ctx[64];
    __shared__ float wsum[32][64];
    int d = t & 63, g = t >> 6;
    float loc = 0.0f;
    for (int r = g; r < NPG; r += 16) loc += sfeat[r * 64 + d];
    p16[g][d] = loc;
    __syncthreads();
    if (t < 64) {
        float s = 0.0f;
#pragma unroll
        for (int j = 0; j < 16; j++) s += p16[j][t];
        meanc[t] = s * (1.0f / NPG);
    }
    __syncthreads();
    if (t < 64) {
        float c = 0.0f;
        for (int i = 0; i < 64; i++) c += meanc[i] * Watt[i * 64 + t];
        ctx[t] = tanhf(c);
    }
    __syncthreads();
    int w = t >> 5, l = t & 31;
    float a0 = 0.0f, a1 = 0.0f;
    float c0 = ctx[l], c1 = ctx[l + 32];
    for (int r = w * 16; r < w * 16 + 16; r++) {
        float v0 = sfeat[r * 64 + l], v1 = sfeat[r * 64 + 32 + l];
        float dp = v0 * c0 + v1 * c1;
#pragma unroll
        for (int o = 16; o; o >>= 1) dp += __shfl_xor_sync(0xffffffffu, dp, o);
        float coef = sigmoidf_(dp);
        a0 += v0 * coef;
        a1 += v1 * coef;
    }
    wsum[w][l] = a0;
    wsum[w][l + 32] = a1;
    __syncthreads();
    if (t < 64) {
        float s = 0.0f;
#pragma unroll
        for (int w2 = 0; w2 < 32; w2++) s += wsum[w2][t];
        g_pool[side][b * 64 + t] = s;
    }
}

// ---------------- bf16x3 tensor-core GEMM (both sides via grid.y) ----------
template <int KIN, int NOUT, bool BIAS, bool RELU>
__global__ void gemm_mma_k(const float* __restrict__ x0, const float* __restrict__ x1,
                           const float* __restrict__ W, const float* __restrict__ bias,
                           float* __restrict__ out0, float* __restrict__ out1) {
    constexpr int KC = 32;
    constexpr int KP = KC / 2;
    constexpr int NT = NOUT / 8;
    constexpr int XS = 20;
    constexpr int WS = 20;
    __shared__ uint32_t Xh[128 * XS];
    __shared__ uint32_t Xl[128 * XS];
    __shared__ uint32_t Wh[NOUT * WS];
    __shared__ uint32_t Wl[NOUT * WS];
    int side = blockIdx.y;
    const float* x = side ? x1 : x0;
    float* out = side ? out1 : out0;
    int tid = threadIdx.x;
    int warp = tid >> 5, lane = tid & 31;
    size_t m0 = (size_t)blockIdx.x * 128;
    float acc[NT][4];
#pragma unroll
    for (int i = 0; i < NT; i++)
#pragma unroll
        for (int j = 0; j < 4; j++) acc[i][j] = 0.0f;

    for (int k0 = 0; k0 < KIN; k0 += KC) {
        for (int i = tid; i < 128 * 8; i += 256) {
            int r = i >> 3, q = i & 7;
            float4 v = *(const float4*)&x[(m0 + r) * KIN + k0 + q * 4];
            uint32_t h0, l0, h1, l1;
            split2(v.x, v.y, h0, l0);
            split2(v.z, v.w, h1, l1);
            Xh[r * XS + q * 2] = h0;     Xh[r * XS + q * 2 + 1] = h1;
            Xl[r * XS + q * 2] = l0;     Xl[r * XS + q * 2 + 1] = l1;
        }
        for (int i = tid; i < NOUT * KP; i += 256) {
            int kp = i / NOUT, n = i % NOUT;
            float w0 = W[(size_t)(k0 + 2 * kp) * NOUT + n];
            float w1 = W[(size_t)(k0 + 2 * kp + 1) * NOUT + n];
            uint32_t h, l;
            split2(w0, w1, h, l);
            Wh[n * WS + kp] = h;
            Wl[n * WS + kp] = l;
        }
        __syncthreads();
#pragma unroll
        for (int s = 0; s < 2; s++) {
            int kb = s * 8 + (lane & 3);
            uint32_t ah[4], al[4];
            int arow = warp * 16 + (lane >> 2);
            ah[0] = Xh[arow * XS + kb];           al[0] = Xl[arow * XS + kb];
            ah[1] = Xh[(arow + 8) * XS + kb];     al[1] = Xl[(arow + 8) * XS + kb];
            ah[2] = Xh[arow * XS + kb + 4];       al[2] = Xl[arow * XS + kb + 4];
            ah[3] = Xh[(arow + 8) * XS + kb + 4]; al[3] = Xl[(arow + 8) * XS + kb + 4];
            int bn = lane >> 2;
#pragma unroll
            for (int nt = 0; nt < NT; nt++) {
                uint32_t bh[2], bl[2];
                int nb = (nt * 8 + bn) * WS;
                bh[0] = Wh[nb + kb]; bh[1] = Wh[nb + kb + 4];
                bl[0] = Wl[nb + kb]; bl[1] = Wl[nb + kb + 4];
                mma_bf16(acc[nt], ah, bh);
                mma_bf16(acc[nt], ah, bl);
                mma_bf16(acc[nt], al, bh);
            }
        }
        __syncthreads();
    }
    size_t row = m0 + warp * 16 + (lane >> 2);
    int col0 = (lane & 3) * 2;
#pragma unroll
    for (int nt = 0; nt < NT; nt++) {
        int c = nt * 8 + col0;
        float b0 = BIAS ? bias[c] : 0.0f, b1 = BIAS ? bias[c + 1] : 0.0f;
        float v0 = acc[nt][0] + b0, v1 = acc[nt][1] + b1;
        float v2 = acc[nt][2] + b0, v3 = acc[nt][3] + b1;
        if (RELU) {
            v0 = fmaxf(v0, 0.f); v1 = fmaxf(v1, 0.f);
            v2 = fmaxf(v2, 0.f); v3 = fmaxf(v3, 0.f);
        }
        *(float2*)&out[row * NOUT + c] = make_float2(v0, v1);
        *(float2*)&out[(row + 8) * NOUT + c] = make_float2(v2, v3);
    }
}

// ---------------- similarity via asymmetric bf16x2 mma (A=bf16, B=hi+lo) ---
// Output is stored fp16 anyway, so A's bf16 residual term is below the
// storage quantization noise. 2 mma per step instead of 3; one less smem slab.
__global__ void sim_mma_k() {
    constexpr int XS = 20;
    int b = blockIdx.z;
    int i0 = blockIdx.y * 128, j0 = blockIdx.x * 128;
    __shared__ uint32_t Ah_s[128 * XS];
    __shared__ uint32_t Bh_s[128 * XS];
    __shared__ uint32_t Bl_s[128 * XS];
    const float* f1 = &g_feat[0][(size_t)(b * NPG + i0) * 64];
    const float* f2 = &g_feat[1][(size_t)(b * NPG + j0) * 64];
    int tid = threadIdx.x;
    int warp = tid >> 5, lane = tid & 31;
    int wm = warp >> 2, wn = warp & 3;
    float acc[4][4][4];
#pragma unroll
    for (int mt = 0; mt < 4; mt++)
#pragma unroll
        for (int nt = 0; nt < 4; nt++)
#pragma unroll
            for (int j = 0; j < 4; j++) acc[mt][nt][j] = 0.0f;

    for (int k0 = 0; k0 < 64; k0 += 32) {
        for (int i = tid; i < 128 * 8; i += 256) {
            int r = i >> 3, q = i & 7;
            float4 va = *(const float4*)&f1[r * 64 + k0 + q * 4];
            float4 vb = *(const float4*)&f2[r * 64 + k0 + q * 4];
            Ah_s[r * XS + q * 2]     = pack2(va.x, va.y);
            Ah_s[r * XS + q * 2 + 1] = pack2(va.z, va.w);
            uint32_t h0, l0, h1, l1;
            split2(vb.x, vb.y, h0, l0);
            split2(vb.z, vb.w, h1, l1);
            Bh_s[r * XS + q * 2] = h0;     Bh_s[r * XS + q * 2 + 1] = h1;
            Bl_s[r * XS + q * 2] = l0;     Bl_s[r * XS + q * 2 + 1] = l1;
        }
        __syncthreads();
#pragma unroll
        for (int s = 0; s < 2; s++) {
            int kb = s * 8 + (lane & 3);
            uint32_t ah[4][4], bh[4][2], bl[4][2];
#pragma unroll
            for (int mt = 0; mt < 4; mt++) {
                int arow = wm * 64 + mt * 16 + (lane >> 2);
                ah[mt][0] = Ah_s[arow * XS + kb];
                ah[mt][1] = Ah_s[(arow + 8) * XS + kb];
                ah[mt][2] = Ah_s[arow * XS + kb + 4];
                ah[mt][3] = Ah_s[(arow + 8) * XS + kb + 4];
            }
#pragma unroll
            for (int nt = 0; nt < 4; nt++) {
                int bnode = wn * 32 + nt * 8 + (lane >> 2);
                bh[nt][0] = Bh_s[bnode * XS + kb];
                bh[nt][1] = Bh_s[bnode * XS + kb + 4];
                bl[nt][0] = Bl_s[bnode * XS + kb];
                bl[nt][1] = Bl_s[bnode * XS + kb + 4];
            }
#pragma unroll
            for (int mt = 0; mt < 4; mt++)
#pragma unroll
                for (int nt = 0; nt < 4; nt++) {
                    mma_bf16(acc[mt][nt], ah[mt], bh[nt]);
                    mma_bf16(acc[mt][nt], ah[mt], bl[nt]);
                }
        }
        __syncthreads();
    }
    float lmin = FLT_MAX, lmax = -FLT_MAX;
    __half* sp = &g_simh[(size_t)b * NPG * NPG];
    int col0 = (lane & 3) * 2;
#pragma unroll
    for (int mt = 0; mt < 4; mt++) {
        size_t r0 = (size_t)(i0 + wm * 64 + mt * 16 + (lane >> 2));
#pragma unroll
        for (int nt = 0; nt < 4; nt++) {
            int c = j0 + wn * 32 + nt * 8 + col0;
            float v0 = acc[mt][nt][0], v1 = acc[mt][nt][1];
            float v2 = acc[mt][nt][2], v3 = acc[mt][nt][3];
            lmin = fminf(lmin, fminf(fminf(v0, v1), fminf(v2, v3)));
            lmax = fmaxf(lmax, fmaxf(fmaxf(v0, v1), fmaxf(v2, v3)));
            *(__half2*)&sp[r0 * NPG + c] = __floats2half2_rn(v0, v1);
            *(__half2*)&sp[(r0 + 8) * NPG + c] = __floats2half2_rn(v2, v3);
        }
    }
    __shared__ float rmin[256], rmax[256];
    rmin[tid] = lmin;
    rmax[tid] = lmax;
    __syncthreads();
    for (int s = 128; s > 0; s >>= 1) {
        if (tid < s) {
            rmin[tid] = fminf(rmin[tid], rmin[tid + s]);
            rmax[tid] = fmaxf(rmax[tid], rmax[tid + s]);
        }
        __syncthreads();
    }
    if (tid == 0) {
        atomicMinFloat(&g_smin[b], rmin[0]);
        atomicMaxFloat(&g_smax[b], rmax[0]);
    }
}

// ---------------- histogram (threshold CDF, half2, 2-way ILP) + head -------
__global__ void hist_final_k(const float* __restrict__ Wt, const float* __restrict__ Wtb,
                             const float* __restrict__ tb, const float* __restrict__ W1,
                             const float* __restrict__ b1, const float* __restrict__ Ws,
                             const float* __restrict__ bs, float* __restrict__ out) {
    int b = blockIdx.x;
    int t = threadIdx.x;
    int lane = t & 31, warp = t >> 5;     // 32 warps
    __shared__ __half2 thr_s[15];
    if (t < 15) {
        float vmin = sigmoidf_(g_smin[b]);
        float vmax = sigmoidf_(g_smax[b]);
        float width = (vmax - vmin) * (1.0f / D_BINS);
        float thr;
        if (width > 0.0f) {
            float bnd = vmin + (float)(t + 1) * width;
            thr = logf(bnd / (1.0f - bnd));
        } else {
            thr = FLT_MAX;
        }
        thr_s[t] = __float2half2_rn(thr);
    }
    __syncthreads();
    __half2 T2[15];
#pragma unroll
    for (int k = 0; k < 15; k++) T2[k] = thr_s[k];

    const uint4* qp = (const uint4*)&g_simh[(size_t)b * NPG * NPG];
    __half2 C2[15];
#pragma unroll
    for (int k = 0; k < 15; k++) C2[k] = __float2half2_rn(0.0f);
    for (int i = t; i < 16384; i += 1024) {
        uint4 qa = qp[i];
        uint4 qb = qp[i + 16384];
        __half2 a0 = *(__half2*)&qa.x, a1 = *(__half2*)&qa.y;
        __half2 a2 = *(__half2*)&qa.z, a3 = *(__half2*)&qa.w;
        __half2 b0 = *(__half2*)&qb.x, b1h = *(__half2*)&qb.y;
        __half2 b2 = *(__half2*)&qb.z, b3 = *(__half2*)&qb.w;
#pragma unroll
        for (int k = 0; k < 15; k++) {
            C2[k] = __hadd2(C2[k], __hge2(a0, T2[k]));
            C2[k] = __hadd2(C2[k], __hge2(a1, T2[k]));
            C2[k] = __hadd2(C2[k], __hge2(a2, T2[k]));
            C2[k] = __hadd2(C2[k], __hge2(a3, T2[k]));
            C2[k] = __hadd2(C2[k], __hge2(b0, T2[k]));
            C2[k] = __hadd2(C2[k], __hge2(b1h, T2[k]));
            C2[k] = __hadd2(C2[k], __hge2(b2, T2[k]));
            C2[k] = __hadd2(C2[k], __hge2(b3, T2[k]));
        }
    }
    __shared__ int red[32][16];
#pragma unroll
    for (int k = 0; k < 15; k++) {
        int c = (int)(__low2float(C2[k]) + __high2float(C2[k]));
#pragma unroll
        for (int o = 16; o; o >>= 1) c += __shfl_xor_sync(0xffffffffu, c, o);
        if (lane == 0) red[warp][k] = c;
    }
    __syncthreads();
    __shared__ int cdf_s[15];
    if (t < 15) {
        int s = 0;
#pragma unroll
        for (int w = 0; w < 32; w++) s += red[w][t];
        cdf_s[t] = s;
    }

    // ---- final head ----
    __shared__ float p1s[64], p2s[64];
    __shared__ float scp[64 * 16];
    __shared__ float feat[32];
    __shared__ float hs[32];
    if (t < 64) {
        p1s[t] = g_pool[0][b * 64 + t];
        p2s[t] = g_pool[1][b * 64 + t];
    }
    __syncthreads();
    if (t < 64) {
        float s[16];
#pragma unroll
        for (int k = 0; k < 16; k++) s[k] = 0.0f;
        for (int j = 0; j < 64; j++) {
            float pj = p2s[j];
            const float* wp = &Wt[(size_t)(t * 64 + j) * 16];
#pragma unroll
            for (int k = 0; k < 16; k++) s[k] += wp[k] * pj;
        }
        float p1v = p1s[t];
#pragma unroll
        for (int k = 0; k < 16; k++) scp[t * 16 + k] = p1v * s[k];
    }
    __syncthreads();
    if (t < 16) {
        float acc = tb[t];
        for (int i = 0; i < 64; i++) acc += scp[i * 16 + t];
        float blk = 0.0f;
        for (int i = 0; i < 64; i++) blk += Wtb[t * 128 + i] * p1s[i];
        for (int i = 0; i < 64; i++) blk += Wtb[t * 128 + 64 + i] * p2s[i];
        float tv = acc + blk;
        feat[t] = fmaxf(tv, 0.0f);
        int C_lo = (t == 0) ? NPG * NPG : cdf_s[t - 1];
        int C_hi = (t == 15) ? 0 : cdf_s[t];
        feat[16 + t] = (float)(C_lo - C_hi) * (1.0f / ((float)NPG * (float)NPG));
    }
    __syncthreads();
    if (t < 32) {
        float acc = b1[t];
        for (int i = 0; i < 32; i++) acc += feat[i] * W1[i * 32 + t];
        hs[t] = fmaxf(acc, 0.0f);
    }
    __syncthreads();
    if (t == 0) {
        float acc = bs[0];
        for (int j = 0; j < 32; j++) acc += hs[j] * Ws[j];
        out[b] = sigmoidf_(acc);
    }
}

// ---------------- launcher ----------------
extern "C" void kernel_launch(void* const* d_in, const int* in_sizes, int n_in,
                              void* d_out, int out_size) {
    const float* x1  = (const float*)d_in[0];
    const float* x2  = (const float*)d_in[1];
    const int* ei1   = (const int*)d_in[2];
    const int* ei2   = (const int*)d_in[3];
    const float* Wc1 = (const float*)d_in[6];
    const float* bc1 = (const float*)d_in[7];
    const float* Wc2 = (const float*)d_in[8];
    const float* bc2 = (const float*)d_in[9];
    const float* Wc3 = (const float*)d_in[10];
    const float* bc3 = (const float*)d_in[11];
    const float* Watt = (const float*)d_in[12];
    const float* Wt  = (const float*)d_in[13];
    const float* Wtb = (const float*)d_in[14];
    const float* tb  = (const float*)d_in[15];
    const float* W1  = (const float*)d_in[16];
    const float* b1  = (const float*)d_in[17];
    const float* Ws  = (const float*)d_in[18];
    const float* bs  = (const float*)d_in[19];
    float* out = (float*)d_out;

    void* p;
    float *a0, *a1, *b0, *b1p, *f0, *f1;
    cudaGetSymbolAddress(&p, g_bufA);
    a0 = (float*)p; a1 = a0 + (size_t)NTOT * D_F1;
    cudaGetSymbolAddress(&p, g_bufB);
    b0 = (float*)p; b1p = b0 + (size_t)NTOT * D_F1;
    cudaGetSymbolAddress(&p, g_feat);
    f0 = (float*)p; f1 = f0 + (size_t)NTOT * D_F3;

    // opt-in to 128 KB dynamic smem for the fused agg+pool kernel (idempotent)
    cudaFuncSetAttribute(agg_pool_k, cudaFuncAttributeMaxDynamicSharedMemorySize,
                         NPG * D_F3 * 4);

    // CSR build for BOTH sides (batched over grid.y); deg_k re-inits smin/smax,
    // scanC_k self-resets degi — no separate init kernel.
    deg_k<<<dim3(NEDGE / 256, 2), 256>>>(ei1 + NEDGE, ei2 + NEDGE);
    scanA_k<<<dim3(256, 2), 256>>>();
    scanC_k<<<dim3(256, 2), 256>>>();
    scatter_k<<<dim3(NEDGE / 256, 2), 256>>>(ei1, ei2);

    // conv pipeline
    agg_k<32, false, false><<<dim3(NB, 2), 1024>>>(x1, x2, nullptr, a0, a1);
    gemm_mma_k<32, 128, true, true><<<dim3(NTOT / 128, 2), 256>>>(a0, a1, Wc1, bc1, b0, b1p);

    gemm_mma_k<128, 96, false, false><<<dim3(NTOT / 128, 2), 256>>>(b0, b1p, Wc2, nullptr, a0, a1);
    agg_k<96, true, true><<<dim3(NB, 2), 1024>>>(a0, a1, bc2, b0, b1p);

    gemm_mma_k<96, 64, false, false><<<dim3(NTOT / 128, 2), 256>>>(b0, b1p, Wc3, nullptr, a0, a1);
    agg_pool_k<<<dim3(NB, 2), 1024, NPG * D_F3 * 4>>>(a0, a1, bc3, f0, f1, Watt);

    sim_mma_k<<<dim3(4, 4, NB), 256>>>();
    hist_final_k<<<NB, 1024>>>(Wt, Wtb, tb, W1, b1, Ws, bs, out);
}